// round 12
// baseline (speedup 1.0000x reference)
#include <cuda_runtime.h>
#include <cuda_fp16.h>
#include <cuda_fp8.h>
#include <math.h>
#include <stdint.h>

typedef __half hf;
typedef __nv_fp8_e4m3 f8;

#define Bq 8
#define Tq 1024
#define Dq 4096
#define Hq 4
#define HSq 1024
#define BT 8192
#define FFq 20480

// ----------------------------- scratch --------------------------------------
__device__ hf g_srcH[(size_t)BT*Dq], g_srcL[(size_t)BT*Dq];
__device__ hf g_attH[(size_t)BT*HSq];
__device__ hf g_WqTH[(size_t)Hq*HSq*Dq], g_WqTL[(size_t)Hq*HSq*Dq];
__device__ hf g_WkTH[(size_t)Hq*HSq*Dq], g_WkTL[(size_t)Hq*HSq*Dq];
__device__ hf g_WvTH[(size_t)Hq*HSq*Dq];
__device__ hf g_qH[(size_t)Hq*BT*HSq], g_qL[(size_t)Hq*BT*HSq];
__device__ hf g_kH[(size_t)Hq*BT*HSq], g_kL[(size_t)Hq*BT*HSq];
__device__ float g_v[(size_t)Hq*BT*HSq];
__device__ hf g_vTH[(size_t)Hq*BT*HSq];
__device__ float g_w[(size_t)Hq*Bq*Tq*Tq];
__device__ hf g_aH[(size_t)Hq*Bq*Tq*Tq];
__device__ float g_ocat[(size_t)BT*Dq];
__device__ float g_srcA[(size_t)BT*Dq];
__device__ hf g_srcAH[(size_t)BT*Dq];
__device__ hf g_dWpTH[(size_t)Hq*Dq*HSq];
__device__ hf g_wpH[(size_t)Hq*BT*Dq];
__device__ hf g_o2H[(size_t)BT*Dq];
__device__ hf g_dWoTH[(size_t)Dq*Dq];
__device__ float g_o3[(size_t)BT*Dq];
__device__ float g_trgf[(size_t)BT*Dq];
__device__ f8 g_ln2F8[(size_t)BT*Dq];
__device__ f8 g_fW1F8[(size_t)FFq*Dq];
__device__ hf g_h1H[(size_t)BT*FFq];
__device__ hf g_fW2TH[(size_t)Dq*FFq];
__device__ float g_ff[(size_t)BT*Dq];

// ----------------------------- helpers --------------------------------------
__device__ __forceinline__ uint32_t smem_u32(const void* p) {
    uint32_t a;
    asm("{ .reg .u64 t; cvta.to.shared.u64 t, %1; cvt.u32.u64 %0, t; }" : "=r"(a) : "l"(p));
    return a;
}
#define CPA16(dst, src) asm volatile("cp.async.cg.shared.global [%0], [%1], 16;" :: "r"((uint32_t)(dst)), "l"(src) : "memory")
#define CP_COMMIT()     asm volatile("cp.async.commit_group;" ::: "memory")
#define CP_WAIT1()      asm volatile("cp.async.wait_group 1;" ::: "memory")
#define LDSM4(r, a) asm volatile("ldmatrix.sync.aligned.m8n8.x4.shared.b16 {%0,%1,%2,%3}, [%4];" \
    : "=r"((r)[0]), "=r"((r)[1]), "=r"((r)[2]), "=r"((r)[3]) : "r"(a))
__device__ __forceinline__ void mma16816(float* d, const uint32_t* a, uint32_t b0, uint32_t b1) {
    asm volatile("mma.sync.aligned.m16n8k16.row.col.f32.f16.f16.f32 "
        "{%0,%1,%2,%3}, {%4,%5,%6,%7}, {%8,%9}, {%0,%1,%2,%3};"
        : "+f"(d[0]), "+f"(d[1]), "+f"(d[2]), "+f"(d[3])
        : "r"(a[0]), "r"(a[1]), "r"(a[2]), "r"(a[3]), "r"(b0), "r"(b1));
}
__device__ __forceinline__ void mma16816h(uint32_t* d, const uint32_t* a, uint32_t b0, uint32_t b1) {
    asm volatile("mma.sync.aligned.m16n8k16.row.col.f16.f16.f16.f16 "
        "{%0,%1}, {%2,%3,%4,%5}, {%6,%7}, {%0,%1};"
        : "+r"(d[0]), "+r"(d[1])
        : "r"(a[0]), "r"(a[1]), "r"(a[2]), "r"(a[3]), "r"(b0), "r"(b1));
}
// fp8 e4m3 mma, k32, fp16 accumulate (fragments byte-identical to f16 k16)
__device__ __forceinline__ void mma16832q(uint32_t* d, const uint32_t* a, uint32_t b0, uint32_t b1) {
    asm volatile("mma.sync.aligned.m16n8k32.row.col.f16.e4m3.e4m3.f16 "
        "{%0,%1}, {%2,%3,%4,%5}, {%6,%7}, {%0,%1};"
        : "+r"(d[0]), "+r"(d[1])
        : "r"(a[0]), "r"(a[1]), "r"(a[2]), "r"(a[3]), "r"(b0), "r"(b1));
}
__device__ __forceinline__ float gelu_exact(float x) { return 0.5f*x*(1.0f+erff(x*0.70710678118654752440f)); }
__device__ __forceinline__ void split_hf(float x, hf& h, hf& l) {
    h = __float2half(x); l = __float2half(x - __half2float(h));
}

#define SSTF  49152
#define SMEMF 98304

// ====== mma.sync split-fp16 GEMM: C = act(alpha*A@B^T + bias) ================
// fp32 accumulate. NPROD=3: ~2^-22 rel. NPROD=1: ~4.9e-4 (error-diluted paths).
// causal: 0 none; 1 skip blocks above diagonal; 2 truncate K at diagonal.
template<int NPROD>
__global__ void __launch_bounds__(256, 1)
gemm_tc(const hf* __restrict__ Ah, const hf* __restrict__ Al,
        const hf* __restrict__ Bh, const hf* __restrict__ Bl,
        const float* __restrict__ bias, float* __restrict__ C,
        hf* __restrict__ Ch, hf* __restrict__ Cl,
        int K, int ldc, int batch2, int aR1, int aR2, int bR1, int bR2,
        long sC1, long sC2, long sB1, float alpha, int act, int causal)
{
    constexpr uint32_t B_OFF  = (NPROD >= 2) ? 32768u : 16384u;
    constexpr uint32_t BL_OFF = 65536u;
    constexpr uint32_t STAGE  = (NPROD == 3) ? 98304u : (NPROD == 2 ? 65536u : 49152u);

    if (causal == 1 && (int)blockIdx.x * 256 > (int)blockIdx.y * 128 + 127) return;
    extern __shared__ __align__(1024) char sm[];
    uint32_t sb = smem_u32(sm);
    int tid = threadIdx.x, wid = tid >> 5, lane = tid & 31;
    int z = blockIdx.z, z1 = z / batch2, z2 = z % batch2;
    long aOff = (long)z1*aR1 + (long)z2*aR2 + blockIdx.y*128;
    long bOff = (long)z1*bR1 + (long)z2*bR2 + blockIdx.x*256;
    int warp_m = (wid & 1) * 64, warp_n = (wid >> 1) * 64;

    float acc[4][8][4];
#pragma unroll
    for (int mt = 0; mt < 4; mt++)
#pragma unroll
        for (int nt = 0; nt < 8; nt++)
#pragma unroll
            for (int r = 0; r < 4; r++) acc[mt][nt][r] = 0.f;

    int nkt = K >> 6;
    if (causal == 2) { int lim = 2 * (int)blockIdx.y + 2; if (lim < nkt) nkt = lim; }

    auto load_stage = [&](int s, int kt) {
        uint32_t base = sb + s * STAGE;
        long kb = (long)kt * 64;
#pragma unroll
        for (int it = 0; it < 4; it++) {
            int idx = tid + it * 256;
            int r = idx >> 3, c = idx & 7;
            uint32_t off = (uint32_t)(r * 128 + ((c ^ (r & 7)) << 4));
            long gi = (aOff + r) * (long)K + kb + c * 8;
            CPA16(base + off, Ah + gi);
            if (NPROD >= 2) CPA16(base + 16384 + off, Al + gi);
        }
#pragma unroll
        for (int it = 0; it < 8; it++) {
            int idx = tid + it * 256;
            int r = idx >> 3, c = idx & 7;
            uint32_t off = (uint32_t)(r * 128 + ((c ^ (r & 7)) << 4));
            long gi = (bOff + r) * (long)K + kb + c * 8;
            CPA16(base + B_OFF + off, Bh + gi);
            if (NPROD == 3) CPA16(base + BL_OFF + off, Bl + gi);
        }
    };

    load_stage(0, 0);
    CP_COMMIT();

    for (int kt = 0; kt < nkt; kt++) {
        int s = kt & 1;
        if (kt + 1 < nkt) load_stage(s ^ 1, kt + 1);
        CP_COMMIT();
        CP_WAIT1();
        __syncthreads();

        uint32_t sA_h = sb + s * STAGE, sA_l = sA_h + 16384;
        uint32_t sB_h = sA_h + B_OFF, sB_l = sA_h + BL_OFF;
#pragma unroll
        for (int ks = 0; ks < 4; ks++) {
            uint32_t ah[4][4], al[4][4];
#pragma unroll
            for (int mt = 0; mt < 4; mt++) {
                int row = warp_m + mt * 16 + (lane & 15);
                int c16 = ks * 2 + (lane >> 4);
                uint32_t off = (uint32_t)(row * 128 + ((c16 ^ (row & 7)) << 4));
                LDSM4(ah[mt], sA_h + off);
                if (NPROD >= 2) LDSM4(al[mt], sA_l + off);
            }
#pragma unroll
            for (int p = 0; p < 4; p++) {
                int row = warp_n + p * 16 + ((lane >> 4) << 3) + (lane & 7);
                int c16 = ks * 2 + ((lane >> 3) & 1);
                uint32_t off = (uint32_t)(row * 128 + ((c16 ^ (row & 7)) << 4));
                uint32_t bh[4];
                LDSM4(bh, sB_h + off);
#pragma unroll
                for (int mt = 0; mt < 4; mt++) {
                    mma16816(acc[mt][2*p],   ah[mt], bh[0], bh[1]);
                    mma16816(acc[mt][2*p+1], ah[mt], bh[2], bh[3]);
                }
                if (NPROD >= 2) {
#pragma unroll
                    for (int mt = 0; mt < 4; mt++) {
                        mma16816(acc[mt][2*p],   al[mt], bh[0], bh[1]);
                        mma16816(acc[mt][2*p+1], al[mt], bh[2], bh[3]);
                    }
                }
                if (NPROD == 3) {
                    uint32_t bl[4];
                    LDSM4(bl, sB_l + off);
#pragma unroll
                    for (int mt = 0; mt < 4; mt++) {
                        mma16816(acc[mt][2*p],   ah[mt], bl[0], bl[1]);
                        mma16816(acc[mt][2*p+1], ah[mt], bl[2], bl[3]);
                    }
                }
            }
        }
        __syncthreads();
    }

    // ---- epilogue ----
    float* Cp = C ? C + z1*sC1 + z2*sC2 : nullptr;
    hf *Chp = Ch ? Ch + z1*sC1 + z2*sC2 : nullptr;
    hf *Clp = Cl ? Cl + z1*sC1 + z2*sC2 : nullptr;
    const float* bp = bias ? bias + z1*sB1 : nullptr;
    int rowBase = blockIdx.y*128 + warp_m + (lane >> 2);
    int colBase = blockIdx.x*256 + warp_n + (lane & 3) * 2;
#pragma unroll
    for (int mt = 0; mt < 4; mt++) {
#pragma unroll
        for (int nt = 0; nt < 8; nt++) {
#pragma unroll
            for (int hh = 0; hh < 2; hh++) {
                int row = rowBase + mt * 16 + hh * 8;
                int col = colBase + nt * 8;
                float x0 = acc[mt][nt][hh*2]     * alpha;
                float x1 = acc[mt][nt][hh*2 + 1] * alpha;
                if (bp) { x0 += bp[col]; x1 += bp[col + 1]; }
                if (act) { x0 = gelu_exact(x0); x1 = gelu_exact(x1); }
                long o = (long)row * ldc + col;
                if (Cp) *(float2*)(Cp + o) = make_float2(x0, x1);
                if (Chp) {
                    hf h0, l0, h1, l1;
                    split_hf(x0, h0, l0); split_hf(x1, h1, l1);
                    *(__half2*)(Chp + o) = __halves2half2(h0, h1);
                    if (Clp) *(__half2*)(Clp + o) = __halves2half2(l0, l1);
                }
            }
        }
    }
}

// ====== fp8 GEMM (FF1): e4m3 x e4m3, fp16 acc, k32; out fp16 ================
// C = act(A@B^T * oscale + bias). B prescaled x64 -> oscale = 1/64.
__global__ void __launch_bounds__(256, 2)
gemm_f8(const f8* __restrict__ A, const f8* __restrict__ B,
        const float* __restrict__ bias, hf* __restrict__ Ch,
        int K, int ldc, float oscale, int act)
{
    extern __shared__ __align__(1024) char sm[];
    uint32_t sb = smem_u32(sm);
    int tid = threadIdx.x, wid = tid >> 5, lane = tid & 31;
    long aOff = blockIdx.y * 128;
    long bOff = blockIdx.x * 256;
    int warp_m = (wid & 1) * 64, warp_n = (wid >> 1) * 64;

    uint32_t hacc[4][8][2];
#pragma unroll
    for (int mt = 0; mt < 4; mt++)
#pragma unroll
        for (int nt = 0; nt < 8; nt++) { hacc[mt][nt][0] = 0u; hacc[mt][nt][1] = 0u; }

    int nkt = K >> 7;   // 128 fp8 per chunk
    auto load_stage = [&](int s, int kt) {
        uint32_t base = sb + s * SSTF;
        long kb = (long)kt * 128;
#pragma unroll
        for (int it = 0; it < 4; it++) {
            int idx = tid + it * 256;
            int r = idx >> 3, c = idx & 7;
            uint32_t off = (uint32_t)(r * 128 + ((c ^ (r & 7)) << 4));
            CPA16(base + off, (const uint8_t*)A + (aOff + r) * (long)K + kb + c * 16);
        }
#pragma unroll
        for (int it = 0; it < 8; it++) {
            int idx = tid + it * 256;
            int r = idx >> 3, c = idx & 7;
            uint32_t off = (uint32_t)(r * 128 + ((c ^ (r & 7)) << 4));
            CPA16(base + 16384 + off, (const uint8_t*)B + (bOff + r) * (long)K + kb + c * 16);
        }
    };

    load_stage(0, 0);
    CP_COMMIT();

    for (int kt = 0; kt < nkt; kt++) {
        int s = kt & 1;
        if (kt + 1 < nkt) load_stage(s ^ 1, kt + 1);
        CP_COMMIT();
        CP_WAIT1();
        __syncthreads();

        uint32_t sA = sb + s * SSTF, sB = sA + 16384;
#pragma unroll
        for (int ks = 0; ks < 4; ks++) {     // each ks = 32 fp8 of K = one k32 mma
            uint32_t ah[4][4];
#pragma unroll
            for (int mt = 0; mt < 4; mt++) {
                int row = warp_m + mt * 16 + (lane & 15);
                int c16 = ks * 2 + (lane >> 4);
                uint32_t off = (uint32_t)(row * 128 + ((c16 ^ (row & 7)) << 4));
                LDSM4(ah[mt], sA + off);
            }
#pragma unroll
            for (int p = 0; p < 4; p++) {
                int row = warp_n + p * 16 + ((lane >> 4) << 3) + (lane & 7);
                int c16 = ks * 2 + ((lane >> 3) & 1);
                uint32_t off = (uint32_t)(row * 128 + ((c16 ^ (row & 7)) << 4));
                uint32_t bh[4];
                LDSM4(bh, sB + off);
#pragma unroll
                for (int mt = 0; mt < 4; mt++) {
                    mma16832q(hacc[mt][2*p],   ah[mt], bh[0], bh[1]);
                    mma16832q(hacc[mt][2*p+1], ah[mt], bh[2], bh[3]);
                }
            }
        }
        __syncthreads();
    }

    int rowBase = blockIdx.y*128 + warp_m + (lane >> 2);
    int colBase = blockIdx.x*256 + warp_n + (lane & 3) * 2;
#pragma unroll
    for (int mt = 0; mt < 4; mt++) {
#pragma unroll
        for (int nt = 0; nt < 8; nt++) {
#pragma unroll
            for (int hh = 0; hh < 2; hh++) {
                int row = rowBase + mt * 16 + hh * 8;
                int col = colBase + nt * 8;
                __half2 hv = *(__half2*)&hacc[mt][nt][hh];
                float x0 = __low2float(hv) * oscale, x1 = __high2float(hv) * oscale;
                if (bias) { x0 += bias[col]; x1 += bias[col + 1]; }
                if (act) { x0 = gelu_exact(x0); x1 = gelu_exact(x1); }
                long o = (long)row * ldc + col;
                *(__half2*)(Ch + o) = __halves2half2(__float2half(x0), __float2half(x1));
            }
        }
    }
}

// ====== FF2 GEMM: fp16 x fp16, fp16 accumulate, 1-product ====================
__global__ void __launch_bounds__(256, 2)
gemm_ff(const hf* __restrict__ A, const hf* __restrict__ B,
        const float* __restrict__ bias, float* __restrict__ C,
        int K, int ldc, int act)
{
    extern __shared__ __align__(1024) char sm[];
    uint32_t sb = smem_u32(sm);
    int tid = threadIdx.x, wid = tid >> 5, lane = tid & 31;
    long aOff = blockIdx.y * 128;
    long bOff = blockIdx.x * 256;
    int warp_m = (wid & 1) * 64, warp_n = (wid >> 1) * 64;

    uint32_t hacc[4][8][2];
#pragma unroll
    for (int mt = 0; mt < 4; mt++)
#pragma unroll
        for (int nt = 0; nt < 8; nt++) { hacc[mt][nt][0] = 0u; hacc[mt][nt][1] = 0u; }

    int nkt = K >> 6;
    auto load_stage = [&](int s, int kt) {
        uint32_t base = sb + s * SSTF;
        long kb = (long)kt * 64;
#pragma unroll
        for (int it = 0; it < 4; it++) {
            int idx = tid + it * 256;
            int r = idx >> 3, c = idx & 7;
            uint32_t off = (uint32_t)(r * 128 + ((c ^ (r & 7)) << 4));
            CPA16(base + off, A + (aOff + r) * (long)K + kb + c * 8);
        }
#pragma unroll
        for (int it = 0; it < 8; it++) {
            int idx = tid + it * 256;
            int r = idx >> 3, c = idx & 7;
            uint32_t off = (uint32_t)(r * 128 + ((c ^ (r & 7)) << 4));
            CPA16(base + 16384 + off, B + (bOff + r) * (long)K + kb + c * 8);
        }
    };

    load_stage(0, 0);
    CP_COMMIT();

    for (int kt = 0; kt < nkt; kt++) {
        int s = kt & 1;
        if (kt + 1 < nkt) load_stage(s ^ 1, kt + 1);
        CP_COMMIT();
        CP_WAIT1();
        __syncthreads();

        uint32_t sA = sb + s * SSTF, sB = sA + 16384;
#pragma unroll
        for (int ks = 0; ks < 4; ks++) {
            uint32_t ah[4][4];
#pragma unroll
            for (int mt = 0; mt < 4; mt++) {
                int row = warp_m + mt * 16 + (lane & 15);
                int c16 = ks * 2 + (lane >> 4);
                uint32_t off = (uint32_t)(row * 128 + ((c16 ^ (row & 7)) << 4));
                LDSM4(ah[mt], sA + off);
            }
#pragma unroll
            for (int p = 0; p < 4; p++) {
                int row = warp_n + p * 16 + ((lane >> 4) << 3) + (lane & 7);
                int c16 = ks * 2 + ((lane >> 3) & 1);
                uint32_t off = (uint32_t)(row * 128 + ((c16 ^ (row & 7)) << 4));
                uint32_t bh[4];
                LDSM4(bh, sB + off);
#pragma unroll
                for (int mt = 0; mt < 4; mt++) {
                    mma16816h(hacc[mt][2*p],   ah[mt], bh[0], bh[1]);
                    mma16816h(hacc[mt][2*p+1], ah[mt], bh[2], bh[3]);
                }
            }
        }
        __syncthreads();
    }

    int rowBase = blockIdx.y*128 + warp_m + (lane >> 2);
    int colBase = blockIdx.x*256 + warp_n + (lane & 3) * 2;
#pragma unroll
    for (int mt = 0; mt < 4; mt++) {
#pragma unroll
        for (int nt = 0; nt < 8; nt++) {
#pragma unroll
            for (int hh = 0; hh < 2; hh++) {
                int row = rowBase + mt * 16 + hh * 8;
                int col = colBase + nt * 8;
                __half2 hv = *(__half2*)&hacc[mt][nt][hh];
                float x0 = __low2float(hv), x1 = __high2float(hv);
                if (bias) { x0 += bias[col]; x1 += bias[col + 1]; }
                if (act) { x0 = gelu_exact(x0); x1 = gelu_exact(x1); }
                long o = (long)row * ldc + col;
                *(float2*)(C + o) = make_float2(x0, x1);
            }
        }
    }
}

// ---------------- fp32 -> (hi,lo) fp16 --------------------------------------
__global__ void conv_hl(const float4* __restrict__ x, hf* __restrict__ h, hf* __restrict__ l) {
    long i = (long)blockIdx.x*256 + threadIdx.x;
    float4 v = x[i];
    hf h0,l0,h1,l1,h2,l2,h3,l3;
    split_hf(v.x,h0,l0); split_hf(v.y,h1,l1); split_hf(v.z,h2,l2); split_hf(v.w,h3,l3);
    __half2* hp = (__half2*)(h + 4*i);
    hp[0]=__halves2half2(h0,h1); hp[1]=__halves2half2(h2,h3);
    if (l) {
        __half2* lp = (__half2*)(l + 4*i);
        lp[0]=__halves2half2(l0,l1); lp[1]=__halves2half2(l2,l3);
    }
}

// ------------- transpose+split: in[z][R][Cc] -> out[z][Cc][R] ----------------
__global__ void tconv(const float* __restrict__ in, hf* __restrict__ oh, hf* __restrict__ ol, int R, int Cc) {
    __shared__ float t[32][33];
    long base = (long)blockIdx.z * R * Cc;
    int c0 = blockIdx.x*32, r0 = blockIdx.y*32;
#pragma unroll
    for (int i = 0; i < 4; i++)
        t[threadIdx.y + i*8][threadIdx.x] = in[base + (long)(r0 + threadIdx.y + i*8)*Cc + c0 + threadIdx.x];
    __syncthreads();
#pragma unroll
    for (int i = 0; i < 4; i++) {
        int c = c0 + threadIdx.y + i*8, r = r0 + threadIdx.x;
        hf h, l; split_hf(t[threadIdx.x][threadIdx.y + i*8], h, l);
        long o = base + (long)c*R + r;
        oh[o] = h;
        if (ol) ol[o] = l;
    }
}

// ------------- transpose -> fp8 x64: in[R][Cc] -> out[Cc][R] -----------------
__global__ void tconv_f8(const float* __restrict__ in, f8* __restrict__ oh, int R, int Cc) {
    __shared__ float t[32][33];
    int c0 = blockIdx.x*32, r0 = blockIdx.y*32;
#pragma unroll
    for (int i = 0; i < 4; i++)
        t[threadIdx.y + i*8][threadIdx.x] = in[(long)(r0 + threadIdx.y + i*8)*Cc + c0 + threadIdx.x];
    __syncthreads();
#pragma unroll
    for (int i = 0; i < 4; i++) {
        int c = c0 + threadIdx.y + i*8, r = r0 + threadIdx.x;
        oh[(long)c*R + r] = f8(t[threadIdx.x][threadIdx.y + i*8] * 64.0f);
    }
}

// ------------------ causal softmax -> fp16 (hi only) -------------------------
__global__ void softmax_causal(const float* __restrict__ w, hf* __restrict__ aH) {
    long row = blockIdx.x;
    int t = (int)(row % Tq), tid = threadIdx.x;
    const float* p = w + row*(long)Tq;
    __shared__ float red[256];
    float vals[4], vmax = -1e30f;
#pragma unroll
    for (int i = 0; i < 4; i++) {
        int j = tid + i*256; float x = p[j]; vals[i] = x;
        if (j <= t && x > vmax) vmax = x;
    }
    red[tid] = vmax; __syncthreads();
    for (int s = 128; s > 0; s >>= 1) { if (tid < s) red[tid] = fmaxf(red[tid], red[tid+s]); __syncthreads(); }
    vmax = red[0]; __syncthreads();
    float sum = 0.f;
#pragma unroll
    for (int i = 0; i < 4; i++) {
        int j = tid + i*256;
        float e = (j <= t) ? expf(vals[i] - vmax) : 0.f;
        vals[i] = e; sum += e;
    }
    red[tid] = sum; __syncthreads();
    for (int s = 128; s > 0; s >>= 1) { if (tid < s) red[tid] += red[tid+s]; __syncthreads(); }
    float inv = 1.f / red[0];
#pragma unroll
    for (int i = 0; i < 4; i++)
        aH[row*(long)Tq + tid + i*256] = __float2half(vals[i]*inv);
}

// --- residual+LN: t = x(+y); out = ln_only ? ln(t) : t+ln(t); fp16/fp8 outs --
__global__ void resln(const float* __restrict__ x, const float* __restrict__ y,
                      const float* __restrict__ g, const float* __restrict__ b,
                      float* __restrict__ out, hf* __restrict__ oh, f8* __restrict__ o8, int ln_only) {
    long row = blockIdx.x;
    int tid = threadIdx.x;
    const float* px = x + row*(long)Dq;
    const float* py = y ? y + row*(long)Dq : nullptr;
    __shared__ float sh[Dq];
    __shared__ float red[256];
    float ls = 0.f;
    for (int i = tid; i < Dq; i += 256) { float t = px[i] + (py ? py[i] : 0.f); sh[i] = t; ls += t; }
    red[tid] = ls; __syncthreads();
    for (int s = 128; s > 0; s >>= 1) { if (tid < s) red[tid] += red[tid+s]; __syncthreads(); }
    float mean = red[0] * (1.0f/Dq); __syncthreads();
    float lv = 0.f;
    for (int i = tid; i < Dq; i += 256) { float d = sh[i]-mean; lv += d*d; }
    red[tid] = lv; __syncthreads();
    for (int s = 128; s > 0; s >>= 1) { if (tid < s) red[tid] += red[tid+s]; __syncthreads(); }
    float rstd = rsqrtf(red[0]*(1.0f/Dq) + 1e-5f);
    for (int i = tid; i < Dq; i += 256) {
        float t = sh[i];
        float l = (t - mean)*rstd*g[i] + b[i];
        float o = ln_only ? l : t + l;
        long oi = row*(long)Dq + i;
        if (out) out[oi] = o;
        if (oh) oh[oi] = __float2half(o);
        if (o8) o8[oi] = f8(o);
    }
}

// -----------------------------------------------------------------------------
extern "C" void kernel_launch(void* const* d_in, const int* in_sizes, int n_in,
                              void* d_out, int out_size)
{
    const float* src=(const float*)d_in[0]; const float* att=(const float*)d_in[1];
    const float* mWq=(const float*)d_in[2]; const float* mbq=(const float*)d_in[3];
    const float* mWk=(const float*)d_in[4]; const float* mbk=(const float*)d_in[5];
    const float* mWv=(const float*)d_in[6]; const float* dWp=(const float*)d_in[7];
    const float* dbp=(const float*)d_in[8]; const float* dWo=(const float*)d_in[9];
    const float* dbo=(const float*)d_in[10]; const float* fW1=(const float*)d_in[11];
    const float* fb1=(const float*)d_in[12]; const float* fW2=(const float*)d_in[13];
    const float* fb2=(const float*)d_in[14]; const float* g1=(const float*)d_in[15];
    const float* b1=(const float*)d_in[16]; const float* g2=(const float*)d_in[17];
    const float* b2=(const float*)d_in[18];
    float* out = (float*)d_out;

#define SYM(T,p,s) T p; cudaGetSymbolAddress((void**)&p, s)
    SYM(hf*,srcH,g_srcH); SYM(hf*,srcL,g_srcL); SYM(hf*,attH,g_attH);
    SYM(hf*,WqTH,g_WqTH); SYM(hf*,WqTL,g_WqTL); SYM(hf*,WkTH,g_WkTH); SYM(hf*,WkTL,g_WkTL);
    SYM(hf*,WvTH,g_WvTH);
    SYM(hf*,qH,g_qH); SYM(hf*,qL,g_qL); SYM(hf*,kH,g_kH); SYM(hf*,kL,g_kL);
    SYM(float*,v,g_v); SYM(hf*,vTH,g_vTH);
    SYM(float*,w,g_w); SYM(hf*,aH,g_aH);
    SYM(float*,ocat,g_ocat); SYM(float*,srcA,g_srcA); SYM(hf*,srcAH,g_srcAH);
    SYM(hf*,dWpTH,g_dWpTH); SYM(hf*,wpH,g_wpH);
    SYM(hf*,o2H,g_o2H); SYM(hf*,dWoTH,g_dWoTH);
    SYM(float*,o3,g_o3); SYM(float*,trgf,g_trgf); SYM(f8*,ln2F8,g_ln2F8);
    SYM(f8*,fW1F8,g_fW1F8); SYM(hf*,h1H,g_h1H);
    SYM(hf*,fW2TH,g_fW2TH); SYM(float*,ff,g_ff);

    cudaFuncSetAttribute(gemm_tc<1>, cudaFuncAttributeMaxDynamicSharedMemorySize, 98304);
    cudaFuncSetAttribute(gemm_tc<3>, cudaFuncAttributeMaxDynamicSharedMemorySize, 196608);
    cudaFuncSetAttribute(gemm_f8,    cudaFuncAttributeMaxDynamicSharedMemorySize, SMEMF);
    cudaFuncSetAttribute(gemm_ff,    cudaFuncAttributeMaxDynamicSharedMemorySize, SMEMF);
    dim3 tb(32, 8);
    const long TT=(long)Tq*Tq, TD=(long)Tq*Dq, BTD=(long)BT*Dq, BTHS=(long)BT*HSq, BTT=(long)Bq*Tq*Tq;

    // operand prep
    conv_hl<<<BTD/1024, 256>>>((const float4*)src, srcH, srcL);
    conv_hl<<<BTHS/1024, 256>>>((const float4*)att, attH, nullptr);
    tconv<<<dim3(HSq/32, Dq/32, Hq), tb>>>(mWq, WqTH, WqTL, Dq, HSq);
    tconv<<<dim3(HSq/32, Dq/32, Hq), tb>>>(mWk, WkTH, WkTL, Dq, HSq);
    tconv<<<dim3(HSq/32, Dq/32, Hq), tb>>>(mWv, WvTH, nullptr, Dq, HSq);
    tconv<<<dim3(Dq/32, HSq/32, Hq), tb>>>(dWp, dWpTH, nullptr, HSq, Dq);
    tconv<<<dim3(Dq/32, Dq/32, 1), tb>>>(dWo, dWoTH, nullptr, Dq, Dq);
    tconv_f8<<<dim3(FFq/32, Dq/32, 1), tb>>>(fW1, fW1F8, Dq, FFq);
    tconv<<<dim3(Dq/32, FFq/32, 1), tb>>>(fW2, fW2TH, nullptr, FFq, Dq);

    // q,k (3-product: softmax amplifies score errors ~1700x), v (1-product)
    gemm_tc<3><<<dim3(4,64,Hq), 256, 196608>>>(srcH, srcL, WqTH, WqTL, mbq, nullptr, qH, qL,
        Dq, HSq, 1, 0,0, HSq,0, BTHS,0, HSq, 1.0f, 0, 0);
    gemm_tc<3><<<dim3(4,64,Hq), 256, 196608>>>(srcH, srcL, WkTH, WkTL, mbk, nullptr, kH, kL,
        Dq, HSq, 1, 0,0, HSq,0, BTHS,0, HSq, 1.0f, 0, 0);
    gemm_tc<1><<<dim3(4,64,Hq), 256, 98304>>>(srcH, nullptr, WvTH, nullptr, nullptr, v, nullptr, nullptr,
        Dq, HSq, 1, 0,0, HSq,0, BTHS,0, 0, 1.0f, 0, 0);
    tconv<<<dim3(HSq/32, Tq/32, Hq*Bq), tb>>>(v, vTH, nullptr, Tq, HSq);
    // scores: per (h,b) [1024,1024] = q @ k^T * 32 ; 3-product, causal block-skip
    gemm_tc<3><<<dim3(4,8,Hq*Bq), 256, 196608>>>(qH, qL, kH, kL, nullptr, w, nullptr, nullptr,
        HSq, Tq, Bq, BT,Tq, BT,Tq, BTT,TT, 0, 32.0f, 0, 1);
    softmax_causal<<<Hq*Bq*Tq, 256>>>(w, aH);
    // o = a @ vT^T : 1-product, K truncated at diagonal
    gemm_tc<1><<<dim3(4,8,Hq*Bq), 256, 98304>>>(aH, nullptr, vTH, nullptr, nullptr, ocat, nullptr, nullptr,
        Tq, Dq, Bq, Bq*Tq,Tq, Bq*HSq,HSq, (long)HSq,TD, 0, 1.0f, 0, 2);
    resln<<<BT, 256>>>(src, ocat, g1, b1, srcA, srcAH, nullptr, 0);
    // wp = att @ dWp^T : 1-product (decoder chain diluted by final LN)
    gemm_tc<1><<<dim3(16,64,Hq), 256, 98304>>>(attH, nullptr, dWpTH, nullptr, dbp, nullptr, wpH, nullptr,
        HSq, Dq, 1, 0,0, Dq,0, BTD,0, Dq, 1.0f, 0, 0);
    // o2 = wp @ srcA^T : K=4096 ; 1-product
    gemm_tc<1><<<dim3(4,8,Hq*Bq), 256, 98304>>>(wpH, nullptr, srcAH, nullptr, nullptr, nullptr, o2H, nullptr,
        Dq, Dq, Bq, BT,Tq, 0,Tq, (long)Tq,TD, 0, 1.0f, 0, 0);
    // o3 = o2 @ dWo^T ; 1-product
    gemm_tc<1><<<dim3(16,64,1), 256, 98304>>>(o2H, nullptr, dWoTH, nullptr, dbo, o3, nullptr, nullptr,
        Dq, Dq, 1, 0,0, 0,0, 0,0, 0, 1.0f, 0, 0);
    resln<<<BT, 256>>>(srcA, o3, g1, b1, trgf, nullptr, nullptr, 0);
    resln<<<BT, 256>>>(trgf, nullptr, g2, b2, nullptr, nullptr, ln2F8, 1);
    // h1 = gelu(ln2 @ (fW1*64)^T / 64 + fb1)  -- fp8 e4m3 (h1 kept fp16)
    gemm_f8<<<dim3(80,64,1), 256, SMEMF>>>(ln2F8, fW1F8, fb1, h1H, Dq, FFq, 1.0f/64.0f, 1);
    // ff = h1 @ fW2^T + fb2  -- fp16 1-product, fp16 acc
    gemm_ff<<<dim3(16,64,1), 256, SMEMF>>>(h1H, fW2TH, fb2, ff, FFq, Dq, 0);
    resln<<<BT, 256>>>(trgf, ff, g2, b2, out, nullptr, nullptr, 1);
}

// round 14
// speedup vs baseline: 1.0244x; 1.0244x over previous
#include <cuda_runtime.h>
#include <cuda_fp16.h>
#include <math.h>
#include <stdint.h>

typedef __half hf;

#define Bq 8
#define Tq 1024
#define Dq 4096
#define Hq 4
#define HSq 1024
#define BT 8192
#define FFq 20480

// ----------------------------- scratch --------------------------------------
__device__ hf g_srcH[(size_t)BT*Dq], g_srcL[(size_t)BT*Dq];
__device__ hf g_attH[(size_t)BT*HSq];
__device__ hf g_WqTH[(size_t)Hq*HSq*Dq], g_WqTL[(size_t)Hq*HSq*Dq];
__device__ hf g_WkTH[(size_t)Hq*HSq*Dq], g_WkTL[(size_t)Hq*HSq*Dq];
__device__ hf g_WvTH[(size_t)Hq*HSq*Dq];
__device__ hf g_qH[(size_t)Hq*BT*HSq], g_qL[(size_t)Hq*BT*HSq];
__device__ hf g_kH[(size_t)Hq*BT*HSq], g_kL[(size_t)Hq*BT*HSq];
__device__ hf g_vH[(size_t)Hq*BT*HSq];
__device__ hf g_vTH[(size_t)Hq*BT*HSq];
__device__ float g_w[(size_t)Hq*Bq*Tq*Tq];
__device__ hf g_aH[(size_t)Hq*Bq*Tq*Tq];
__device__ float g_ocat[(size_t)BT*Dq];
__device__ float g_srcA[(size_t)BT*Dq];
__device__ hf g_srcAH[(size_t)BT*Dq];
__device__ hf g_dWpTH[(size_t)Hq*Dq*HSq];
__device__ hf g_wpH[(size_t)Hq*BT*Dq];
__device__ hf g_o2H[(size_t)BT*Dq];
__device__ hf g_dWoTH[(size_t)Dq*Dq];
__device__ float g_o3[(size_t)BT*Dq];
__device__ float g_trgf[(size_t)BT*Dq];
__device__ hf g_ln2H[(size_t)BT*Dq];
__device__ hf g_fW1TH[(size_t)FFq*Dq];
__device__ hf g_h1H[(size_t)BT*FFq];
__device__ hf g_fW2TH[(size_t)Dq*FFq];
__device__ float g_ff[(size_t)BT*Dq];

// ----------------------------- helpers --------------------------------------
__device__ __forceinline__ uint32_t smem_u32(const void* p) {
    uint32_t a;
    asm("{ .reg .u64 t; cvta.to.shared.u64 t, %1; cvt.u32.u64 %0, t; }" : "=r"(a) : "l"(p));
    return a;
}
#define CPA16(dst, src) asm volatile("cp.async.cg.shared.global [%0], [%1], 16;" :: "r"((uint32_t)(dst)), "l"(src) : "memory")
#define CP_COMMIT()     asm volatile("cp.async.commit_group;" ::: "memory")
#define CP_WAIT1()      asm volatile("cp.async.wait_group 1;" ::: "memory")
#define LDSM4(r, a) asm volatile("ldmatrix.sync.aligned.m8n8.x4.shared.b16 {%0,%1,%2,%3}, [%4];" \
    : "=r"((r)[0]), "=r"((r)[1]), "=r"((r)[2]), "=r"((r)[3]) : "r"(a))
__device__ __forceinline__ void mma16816(float* d, const uint32_t* a, uint32_t b0, uint32_t b1) {
    asm volatile("mma.sync.aligned.m16n8k16.row.col.f32.f16.f16.f32 "
        "{%0,%1,%2,%3}, {%4,%5,%6,%7}, {%8,%9}, {%0,%1,%2,%3};"
        : "+f"(d[0]), "+f"(d[1]), "+f"(d[2]), "+f"(d[3])
        : "r"(a[0]), "r"(a[1]), "r"(a[2]), "r"(a[3]), "r"(b0), "r"(b1));
}
__device__ __forceinline__ void mma16816h(uint32_t* d, const uint32_t* a, uint32_t b0, uint32_t b1) {
    asm volatile("mma.sync.aligned.m16n8k16.row.col.f16.f16.f16.f16 "
        "{%0,%1}, {%2,%3,%4,%5}, {%6,%7}, {%0,%1};"
        : "+r"(d[0]), "+r"(d[1])
        : "r"(a[0]), "r"(a[1]), "r"(a[2]), "r"(a[3]), "r"(b0), "r"(b1));
}
__device__ __forceinline__ float gelu_exact(float x) { return 0.5f*x*(1.0f+erff(x*0.70710678118654752440f)); }
__device__ __forceinline__ void split_hf(float x, hf& h, hf& l) {
    h = __float2half(x); l = __float2half(x - __half2float(h));
}

#define SSTF  49152
#define SMEMF 98304

// ====== mma.sync split-fp16 GEMM: C = act(alpha*A@B^T + bias) ================
// fp32 accumulate. NPROD=3: Ah*Bh+Al*Bh+Ah*Bl (~2^-22 rel — REQUIRED for the
// attention score path: softmax shifts weights by exp(score abs err), so score
// error must be <<1; 2-prod gives ~0.45 and fails hard). NPROD=1: ~4.9e-4,
// only for paths diluted by the final LN (decoder chain, v, AV, FF).
// causal: 0 none; 1 skip blocks above diagonal; 2 truncate K at diagonal.
// CTA tile 128x256, 8 warps (warp tile 64x64), K-chunk 64, cp.async 2-stage.
template<int NPROD>
__global__ void __launch_bounds__(256, 1)
gemm_tc(const hf* __restrict__ Ah, const hf* __restrict__ Al,
        const hf* __restrict__ Bh, const hf* __restrict__ Bl,
        const float* __restrict__ bias, float* __restrict__ C,
        hf* __restrict__ Ch, hf* __restrict__ Cl,
        int K, int ldc, int batch2, int aR1, int aR2, int bR1, int bR2,
        long sC1, long sC2, long sB1, float alpha, int act, int causal)
{
    constexpr uint32_t B_OFF  = (NPROD >= 2) ? 32768u : 16384u;
    constexpr uint32_t BL_OFF = 65536u;
    constexpr uint32_t STAGE  = (NPROD == 3) ? 98304u : (NPROD == 2 ? 65536u : 49152u);

    if (causal == 1 && (int)blockIdx.x * 256 > (int)blockIdx.y * 128 + 127) return;
    extern __shared__ __align__(1024) char sm[];
    uint32_t sb = smem_u32(sm);
    int tid = threadIdx.x, wid = tid >> 5, lane = tid & 31;
    int z = blockIdx.z, z1 = z / batch2, z2 = z % batch2;
    long aOff = (long)z1*aR1 + (long)z2*aR2 + blockIdx.y*128;
    long bOff = (long)z1*bR1 + (long)z2*bR2 + blockIdx.x*256;
    int warp_m = (wid & 1) * 64, warp_n = (wid >> 1) * 64;

    float acc[4][8][4];
#pragma unroll
    for (int mt = 0; mt < 4; mt++)
#pragma unroll
        for (int nt = 0; nt < 8; nt++)
#pragma unroll
            for (int r = 0; r < 4; r++) acc[mt][nt][r] = 0.f;

    int nkt = K >> 6;
    if (causal == 2) { int lim = 2 * (int)blockIdx.y + 2; if (lim < nkt) nkt = lim; }

    auto load_stage = [&](int s, int kt) {
        uint32_t base = sb + s * STAGE;
        long kb = (long)kt * 64;
#pragma unroll
        for (int it = 0; it < 4; it++) {
            int idx = tid + it * 256;
            int r = idx >> 3, c = idx & 7;
            uint32_t off = (uint32_t)(r * 128 + ((c ^ (r & 7)) << 4));
            long gi = (aOff + r) * (long)K + kb + c * 8;
            CPA16(base + off, Ah + gi);
            if (NPROD >= 2) CPA16(base + 16384 + off, Al + gi);
        }
#pragma unroll
        for (int it = 0; it < 8; it++) {
            int idx = tid + it * 256;
            int r = idx >> 3, c = idx & 7;
            uint32_t off = (uint32_t)(r * 128 + ((c ^ (r & 7)) << 4));
            long gi = (bOff + r) * (long)K + kb + c * 8;
            CPA16(base + B_OFF + off, Bh + gi);
            if (NPROD == 3) CPA16(base + BL_OFF + off, Bl + gi);
        }
    };

    load_stage(0, 0);
    CP_COMMIT();

    for (int kt = 0; kt < nkt; kt++) {
        int s = kt & 1;
        if (kt + 1 < nkt) load_stage(s ^ 1, kt + 1);
        CP_COMMIT();
        CP_WAIT1();
        __syncthreads();

        uint32_t sA_h = sb + s * STAGE, sA_l = sA_h + 16384;
        uint32_t sB_h = sA_h + B_OFF, sB_l = sA_h + BL_OFF;
#pragma unroll
        for (int ks = 0; ks < 4; ks++) {
            uint32_t ah[4][4], al[4][4];
#pragma unroll
            for (int mt = 0; mt < 4; mt++) {
                int row = warp_m + mt * 16 + (lane & 15);
                int c16 = ks * 2 + (lane >> 4);
                uint32_t off = (uint32_t)(row * 128 + ((c16 ^ (row & 7)) << 4));
                LDSM4(ah[mt], sA_h + off);
                if (NPROD >= 2) LDSM4(al[mt], sA_l + off);
            }
#pragma unroll
            for (int p = 0; p < 4; p++) {
                int row = warp_n + p * 16 + ((lane >> 4) << 3) + (lane & 7);
                int c16 = ks * 2 + ((lane >> 3) & 1);
                uint32_t off = (uint32_t)(row * 128 + ((c16 ^ (row & 7)) << 4));
                uint32_t bh[4];
                LDSM4(bh, sB_h + off);
#pragma unroll
                for (int mt = 0; mt < 4; mt++) {
                    mma16816(acc[mt][2*p],   ah[mt], bh[0], bh[1]);
                    mma16816(acc[mt][2*p+1], ah[mt], bh[2], bh[3]);
                }
                if (NPROD >= 2) {
#pragma unroll
                    for (int mt = 0; mt < 4; mt++) {
                        mma16816(acc[mt][2*p],   al[mt], bh[0], bh[1]);
                        mma16816(acc[mt][2*p+1], al[mt], bh[2], bh[3]);
                    }
                }
                if (NPROD == 3) {
                    uint32_t bl[4];
                    LDSM4(bl, sB_l + off);
#pragma unroll
                    for (int mt = 0; mt < 4; mt++) {
                        mma16816(acc[mt][2*p],   ah[mt], bl[0], bl[1]);
                        mma16816(acc[mt][2*p+1], ah[mt], bl[2], bl[3]);
                    }
                }
            }
        }
        __syncthreads();
    }

    // ---- epilogue ----
    float* Cp = C ? C + z1*sC1 + z2*sC2 : nullptr;
    hf *Chp = Ch ? Ch + z1*sC1 + z2*sC2 : nullptr;
    hf *Clp = Cl ? Cl + z1*sC1 + z2*sC2 : nullptr;
    const float* bp = bias ? bias + z1*sB1 : nullptr;
    int rowBase = blockIdx.y*128 + warp_m + (lane >> 2);
    int colBase = blockIdx.x*256 + warp_n + (lane & 3) * 2;
#pragma unroll
    for (int mt = 0; mt < 4; mt++) {
#pragma unroll
        for (int nt = 0; nt < 8; nt++) {
#pragma unroll
            for (int hh = 0; hh < 2; hh++) {
                int row = rowBase + mt * 16 + hh * 8;
                int col = colBase + nt * 8;
                float x0 = acc[mt][nt][hh*2]     * alpha;
                float x1 = acc[mt][nt][hh*2 + 1] * alpha;
                if (bp) { x0 += bp[col]; x1 += bp[col + 1]; }
                if (act) { x0 = gelu_exact(x0); x1 = gelu_exact(x1); }
                long o = (long)row * ldc + col;
                if (Cp) *(float2*)(Cp + o) = make_float2(x0, x1);
                if (Chp) {
                    hf h0, l0, h1, l1;
                    split_hf(x0, h0, l0); split_hf(x1, h1, l1);
                    *(__half2*)(Chp + o) = __halves2half2(h0, h1);
                    if (Clp) *(__half2*)(Clp + o) = __halves2half2(l0, l1);
                }
            }
        }
    }
}

// ====== FF GEMM: fp16 x fp16, fp16 accumulate, 1-product ====================
__global__ void __launch_bounds__(256, 2)
gemm_ff(const hf* __restrict__ A, const hf* __restrict__ B,
        const float* __restrict__ bias, float* __restrict__ C, hf* __restrict__ Ch,
        int K, int ldc, int act)
{
    extern __shared__ __align__(1024) char sm[];
    uint32_t sb = smem_u32(sm);
    int tid = threadIdx.x, wid = tid >> 5, lane = tid & 31;
    long aOff = blockIdx.y * 128;
    long bOff = blockIdx.x * 256;
    int warp_m = (wid & 1) * 64, warp_n = (wid >> 1) * 64;

    uint32_t hacc[4][8][2];
#pragma unroll
    for (int mt = 0; mt < 4; mt++)
#pragma unroll
        for (int nt = 0; nt < 8; nt++) { hacc[mt][nt][0] = 0u; hacc[mt][nt][1] = 0u; }

    int nkt = K >> 6;
    auto load_stage = [&](int s, int kt) {
        uint32_t base = sb + s * SSTF;
        long kb = (long)kt * 64;
#pragma unroll
        for (int it = 0; it < 4; it++) {
            int idx = tid + it * 256;
            int r = idx >> 3, c = idx & 7;
            uint32_t off = (uint32_t)(r * 128 + ((c ^ (r & 7)) << 4));
            CPA16(base + off, A + (aOff + r) * (long)K + kb + c * 8);
        }
#pragma unroll
        for (int it = 0; it < 8; it++) {
            int idx = tid + it * 256;
            int r = idx >> 3, c = idx & 7;
            uint32_t off = (uint32_t)(r * 128 + ((c ^ (r & 7)) << 4));
            CPA16(base + 16384 + off, B + (bOff + r) * (long)K + kb + c * 8);
        }
    };

    load_stage(0, 0);
    CP_COMMIT();

    for (int kt = 0; kt < nkt; kt++) {
        int s = kt & 1;
        if (kt + 1 < nkt) load_stage(s ^ 1, kt + 1);
        CP_COMMIT();
        CP_WAIT1();
        __syncthreads();

        uint32_t sA = sb + s * SSTF, sB = sA + 16384;
#pragma unroll
        for (int ks = 0; ks < 4; ks++) {
            uint32_t ah[4][4];
#pragma unroll
            for (int mt = 0; mt < 4; mt++) {
                int row = warp_m + mt * 16 + (lane & 15);
                int c16 = ks * 2 + (lane >> 4);
                uint32_t off = (uint32_t)(row * 128 + ((c16 ^ (row & 7)) << 4));
                LDSM4(ah[mt], sA + off);
            }
#pragma unroll
            for (int p = 0; p < 4; p++) {
                int row = warp_n + p * 16 + ((lane >> 4) << 3) + (lane & 7);
                int c16 = ks * 2 + ((lane >> 3) & 1);
                uint32_t off = (uint32_t)(row * 128 + ((c16 ^ (row & 7)) << 4));
                uint32_t bh[4];
                LDSM4(bh, sB + off);
#pragma unroll
                for (int mt = 0; mt < 4; mt++) {
                    mma16816h(hacc[mt][2*p],   ah[mt], bh[0], bh[1]);
                    mma16816h(hacc[mt][2*p+1], ah[mt], bh[2], bh[3]);
                }
            }
        }
        __syncthreads();
    }

    int rowBase = blockIdx.y*128 + warp_m + (lane >> 2);
    int colBase = blockIdx.x*256 + warp_n + (lane & 3) * 2;
#pragma unroll
    for (int mt = 0; mt < 4; mt++) {
#pragma unroll
        for (int nt = 0; nt < 8; nt++) {
#pragma unroll
            for (int hh = 0; hh < 2; hh++) {
                int row = rowBase + mt * 16 + hh * 8;
                int col = colBase + nt * 8;
                __half2 hv = *(__half2*)&hacc[mt][nt][hh];
                float x0 = __low2float(hv), x1 = __high2float(hv);
                if (bias) { x0 += bias[col]; x1 += bias[col + 1]; }
                if (act) { x0 = gelu_exact(x0); x1 = gelu_exact(x1); }
                long o = (long)row * ldc + col;
                if (C) *(float2*)(C + o) = make_float2(x0, x1);
                if (Ch) *(__half2*)(Ch + o) = __halves2half2(__float2half(x0), __float2half(x1));
            }
        }
    }
}

// ---------------- fp32 -> (hi,lo) fp16 --------------------------------------
__global__ void conv_hl(const float4* __restrict__ x, hf* __restrict__ h, hf* __restrict__ l) {
    long i = (long)blockIdx.x*256 + threadIdx.x;
    float4 v = x[i];
    hf h0,l0,h1,l1,h2,l2,h3,l3;
    split_hf(v.x,h0,l0); split_hf(v.y,h1,l1); split_hf(v.z,h2,l2); split_hf(v.w,h3,l3);
    __half2* hp = (__half2*)(h + 4*i);
    hp[0]=__halves2half2(h0,h1); hp[1]=__halves2half2(h2,h3);
    if (l) {
        __half2* lp = (__half2*)(l + 4*i);
        lp[0]=__halves2half2(l0,l1); lp[1]=__halves2half2(l2,l3);
    }
}

// ------------- transpose+split: in[z][R][Cc] -> out[z][Cc][R] (fp32 in) ------
__global__ void tconv(const float* __restrict__ in, hf* __restrict__ oh, hf* __restrict__ ol, int R, int Cc) {
    __shared__ float t[32][33];
    long base = (long)blockIdx.z * R * Cc;
    int c0 = blockIdx.x*32, r0 = blockIdx.y*32;
#pragma unroll
    for (int i = 0; i < 4; i++)
        t[threadIdx.y + i*8][threadIdx.x] = in[base + (long)(r0 + threadIdx.y + i*8)*Cc + c0 + threadIdx.x];
    __syncthreads();
#pragma unroll
    for (int i = 0; i < 4; i++) {
        int c = c0 + threadIdx.y + i*8, r = r0 + threadIdx.x;
        hf h, l; split_hf(t[threadIdx.x][threadIdx.y + i*8], h, l);
        long o = base + (long)c*R + r;
        oh[o] = h;
        if (ol) ol[o] = l;
    }
}

// ------------- transpose (fp16 in -> fp16 out): in[z][R][Cc] -> out[z][Cc][R]
__global__ void tconv_h(const hf* __restrict__ in, hf* __restrict__ oh, int R, int Cc) {
    __shared__ hf t[32][34];
    long base = (long)blockIdx.z * R * Cc;
    int c0 = blockIdx.x*32, r0 = blockIdx.y*32;
#pragma unroll
    for (int i = 0; i < 4; i++)
        t[threadIdx.y + i*8][threadIdx.x] = in[base + (long)(r0 + threadIdx.y + i*8)*Cc + c0 + threadIdx.x];
    __syncthreads();
#pragma unroll
    for (int i = 0; i < 4; i++) {
        int c = c0 + threadIdx.y + i*8, r = r0 + threadIdx.x;
        oh[base + (long)c*R + r] = t[threadIdx.x][threadIdx.y + i*8];
    }
}

// ------------------ causal softmax -> fp16 (hi only) -------------------------
__global__ void softmax_causal(const float* __restrict__ w, hf* __restrict__ aH) {
    long row = blockIdx.x;
    int t = (int)(row % Tq), tid = threadIdx.x;
    const float* p = w + row*(long)Tq;
    __shared__ float red[256];
    float vals[4], vmax = -1e30f;
#pragma unroll
    for (int i = 0; i < 4; i++) {
        int j = tid + i*256; float x = p[j]; vals[i] = x;
        if (j <= t && x > vmax) vmax = x;
    }
    red[tid] = vmax; __syncthreads();
    for (int s = 128; s > 0; s >>= 1) { if (tid < s) red[tid] = fmaxf(red[tid], red[tid+s]); __syncthreads(); }
    vmax = red[0]; __syncthreads();
    float sum = 0.f;
#pragma unroll
    for (int i = 0; i < 4; i++) {
        int j = tid + i*256;
        float e = (j <= t) ? expf(vals[i] - vmax) : 0.f;
        vals[i] = e; sum += e;
    }
    red[tid] = sum; __syncthreads();
    for (int s = 128; s > 0; s >>= 1) { if (tid < s) red[tid] += red[tid+s]; __syncthreads(); }
    float inv = 1.f / red[0];
#pragma unroll
    for (int i = 0; i < 4; i++)
        aH[row*(long)Tq + tid + i*256] = __float2half(vals[i]*inv);
}

// --- residual+LN: t = x(+y); out = ln_only ? ln(t) : t+ln(t); fp16 out opt ---
__global__ void resln(const float* __restrict__ x, const float* __restrict__ y,
                      const float* __restrict__ g, const float* __restrict__ b,
                      float* __restrict__ out, hf* __restrict__ oh, int ln_only) {
    long row = blockIdx.x;
    int tid = threadIdx.x;
    const float* px = x + row*(long)Dq;
    const float* py = y ? y + row*(long)Dq : nullptr;
    __shared__ float sh[Dq];
    __shared__ float red[256];
    float ls = 0.f;
    for (int i = tid; i < Dq; i += 256) { float t = px[i] + (py ? py[i] : 0.f); sh[i] = t; ls += t; }
    red[tid] = ls; __syncthreads();
    for (int s = 128; s > 0; s >>= 1) { if (tid < s) red[tid] += red[tid+s]; __syncthreads(); }
    float mean = red[0] * (1.0f/Dq); __syncthreads();
    float lv = 0.f;
    for (int i = tid; i < Dq; i += 256) { float d = sh[i]-mean; lv += d*d; }
    red[tid] = lv; __syncthreads();
    for (int s = 128; s > 0; s >>= 1) { if (tid < s) red[tid] += red[tid+s]; __syncthreads(); }
    float rstd = rsqrtf(red[0]*(1.0f/Dq) + 1e-5f);
    for (int i = tid; i < Dq; i += 256) {
        float t = sh[i];
        float l = (t - mean)*rstd*g[i] + b[i];
        float o = ln_only ? l : t + l;
        long oi = row*(long)Dq + i;
        if (out) out[oi] = o;
        if (oh) oh[oi] = __float2half(o);
    }
}

// --- fused double-LN: t = x+y; trgf = t+ln(t,g1,b1); ln2h = ln(trgf,g2,b2) ---
__global__ void resln2(const float* __restrict__ x, const float* __restrict__ y,
                       const float* __restrict__ g1, const float* __restrict__ b1,
                       const float* __restrict__ g2, const float* __restrict__ b2,
                       float* __restrict__ trgf, hf* __restrict__ ln2h) {
    long row = blockIdx.x;
    int tid = threadIdx.x;
    const float* px = x + row*(long)Dq;
    const float* py = y + row*(long)Dq;
    __shared__ float sh[Dq];
    __shared__ float red[256];
    float ls = 0.f;
    for (int i = tid; i < Dq; i += 256) { float t = px[i] + py[i]; sh[i] = t; ls += t; }
    red[tid] = ls; __syncthreads();
    for (int s = 128; s > 0; s >>= 1) { if (tid < s) red[tid] += red[tid+s]; __syncthreads(); }
    float mean = red[0] * (1.0f/Dq); __syncthreads();
    float lv = 0.f;
    for (int i = tid; i < Dq; i += 256) { float d = sh[i]-mean; lv += d*d; }
    red[tid] = lv; __syncthreads();
    for (int s = 128; s > 0; s >>= 1) { if (tid < s) red[tid] += red[tid+s]; __syncthreads(); }
    float rstd = rsqrtf(red[0]*(1.0f/Dq) + 1e-5f);
    __syncthreads();
    float ls2 = 0.f;
    for (int i = tid; i < Dq; i += 256) {
        float t = sh[i];
        float o = t + (t - mean)*rstd*g1[i] + b1[i];
        sh[i] = o; ls2 += o;
        trgf[row*(long)Dq + i] = o;
    }
    red[tid] = ls2; __syncthreads();
    for (int s = 128; s > 0; s >>= 1) { if (tid < s) red[tid] += red[tid+s]; __syncthreads(); }
    float mean2 = red[0] * (1.0f/Dq); __syncthreads();
    float lv2 = 0.f;
    for (int i = tid; i < Dq; i += 256) { float d = sh[i]-mean2; lv2 += d*d; }
    red[tid] = lv2; __syncthreads();
    for (int s = 128; s > 0; s >>= 1) { if (tid < s) red[tid] += red[tid+s]; __syncthreads(); }
    float rstd2 = rsqrtf(red[0]*(1.0f/Dq) + 1e-5f);
    for (int i = tid; i < Dq; i += 256)
        ln2h[row*(long)Dq + i] = __float2half((sh[i] - mean2)*rstd2*g2[i] + b2[i]);
}

// -----------------------------------------------------------------------------
extern "C" void kernel_launch(void* const* d_in, const int* in_sizes, int n_in,
                              void* d_out, int out_size)
{
    const float* src=(const float*)d_in[0]; const float* att=(const float*)d_in[1];
    const float* mWq=(const float*)d_in[2]; const float* mbq=(const float*)d_in[3];
    const float* mWk=(const float*)d_in[4]; const float* mbk=(const float*)d_in[5];
    const float* mWv=(const float*)d_in[6]; const float* dWp=(const float*)d_in[7];
    const float* dbp=(const float*)d_in[8]; const float* dWo=(const float*)d_in[9];
    const float* dbo=(const float*)d_in[10]; const float* fW1=(const float*)d_in[11];
    const float* fb1=(const float*)d_in[12]; const float* fW2=(const float*)d_in[13];
    const float* fb2=(const float*)d_in[14]; const float* g1=(const float*)d_in[15];
    const float* b1=(const float*)d_in[16]; const float* g2=(const float*)d_in[17];
    const float* b2=(const float*)d_in[18];
    float* out = (float*)d_out;

#define SYM(T,p,s) T p; cudaGetSymbolAddress((void**)&p, s)
    SYM(hf*,srcH,g_srcH); SYM(hf*,srcL,g_srcL); SYM(hf*,attH,g_attH);
    SYM(hf*,WqTH,g_WqTH); SYM(hf*,WqTL,g_WqTL); SYM(hf*,WkTH,g_WkTH); SYM(hf*,WkTL,g_WkTL);
    SYM(hf*,WvTH,g_WvTH);
    SYM(hf*,qH,g_qH); SYM(hf*,qL,g_qL); SYM(hf*,kH,g_kH); SYM(hf*,kL,g_kL);
    SYM(hf*,vH,g_vH); SYM(hf*,vTH,g_vTH);
    SYM(float*,w,g_w); SYM(hf*,aH,g_aH);
    SYM(float*,ocat,g_ocat); SYM(float*,srcA,g_srcA); SYM(hf*,srcAH,g_srcAH);
    SYM(hf*,dWpTH,g_dWpTH); SYM(hf*,wpH,g_wpH);
    SYM(hf*,o2H,g_o2H); SYM(hf*,dWoTH,g_dWoTH);
    SYM(float*,o3,g_o3); SYM(float*,trgf,g_trgf); SYM(hf*,ln2H,g_ln2H);
    SYM(hf*,fW1TH,g_fW1TH); SYM(hf*,h1H,g_h1H);
    SYM(hf*,fW2TH,g_fW2TH); SYM(float*,ff,g_ff);

    cudaFuncSetAttribute(gemm_tc<1>, cudaFuncAttributeMaxDynamicSharedMemorySize, 98304);
    cudaFuncSetAttribute(gemm_tc<3>, cudaFuncAttributeMaxDynamicSharedMemorySize, 196608);
    cudaFuncSetAttribute(gemm_ff,    cudaFuncAttributeMaxDynamicSharedMemorySize, SMEMF);
    dim3 tb(32, 8);
    const long TT=(long)Tq*Tq, TD=(long)Tq*Dq, BTD=(long)BT*Dq, BTHS=(long)BT*HSq, BTT=(long)Bq*Tq*Tq;

    // operand prep
    conv_hl<<<BTD/1024, 256>>>((const float4*)src, srcH, srcL);
    conv_hl<<<BTHS/1024, 256>>>((const float4*)att, attH, nullptr);
    tconv<<<dim3(HSq/32, Dq/32, Hq), tb>>>(mWq, WqTH, WqTL, Dq, HSq);
    tconv<<<dim3(HSq/32, Dq/32, Hq), tb>>>(mWk, WkTH, WkTL, Dq, HSq);
    tconv<<<dim3(HSq/32, Dq/32, Hq), tb>>>(mWv, WvTH, nullptr, Dq, HSq);
    tconv<<<dim3(Dq/32, HSq/32, Hq), tb>>>(dWp, dWpTH, nullptr, HSq, Dq);
    tconv<<<dim3(Dq/32, Dq/32, 1), tb>>>(dWo, dWoTH, nullptr, Dq, Dq);
    tconv<<<dim3(FFq/32, Dq/32, 1), tb>>>(fW1, fW1TH, nullptr, Dq, FFq);
    tconv<<<dim3(Dq/32, FFq/32, 1), tb>>>(fW2, fW2TH, nullptr, FFq, Dq);

    // q,k: 3-product (score abs error must be <<1 for softmax), v: 1-product
    gemm_tc<3><<<dim3(4,64,Hq), 256, 196608>>>(srcH, srcL, WqTH, WqTL, mbq, nullptr, qH, qL,
        Dq, HSq, 1, 0,0, HSq,0, BTHS,0, HSq, 1.0f, 0, 0);
    gemm_tc<3><<<dim3(4,64,Hq), 256, 196608>>>(srcH, srcL, WkTH, WkTL, mbk, nullptr, kH, kL,
        Dq, HSq, 1, 0,0, HSq,0, BTHS,0, HSq, 1.0f, 0, 0);
    gemm_tc<1><<<dim3(4,64,Hq), 256, 98304>>>(srcH, nullptr, WvTH, nullptr, nullptr, nullptr, vH, nullptr,
        Dq, HSq, 1, 0,0, HSq,0, BTHS,0, 0, 1.0f, 0, 0);
    tconv_h<<<dim3(HSq/32, Tq/32, Hq*Bq), tb>>>(vH, vTH, Tq, HSq);
    // scores: 3-product, causal block-skip
    gemm_tc<3><<<dim3(4,8,Hq*Bq), 256, 196608>>>(qH, qL, kH, kL, nullptr, w, nullptr, nullptr,
        HSq, Tq, Bq, BT,Tq, BT,Tq, BTT,TT, 0, 32.0f, 0, 1);
    softmax_causal<<<Hq*Bq*Tq, 256>>>(w, aH);
    // o = a @ vT^T : 1-product, K truncated at diagonal
    gemm_tc<1><<<dim3(4,8,Hq*Bq), 256, 98304>>>(aH, nullptr, vTH, nullptr, nullptr, ocat, nullptr, nullptr,
        Tq, Dq, Bq, Bq*Tq,Tq, Bq*HSq,HSq, (long)HSq,TD, 0, 1.0f, 0, 2);
    resln<<<BT, 256>>>(src, ocat, g1, b1, srcA, srcAH, 0);
    // wp = att @ dWp^T : 1-product (decoder chain diluted by final LN)
    gemm_tc<1><<<dim3(16,64,Hq), 256, 98304>>>(attH, nullptr, dWpTH, nullptr, dbp, nullptr, wpH, nullptr,
        HSq, Dq, 1, 0,0, Dq,0, BTD,0, Dq, 1.0f, 0, 0);
    // o2 = wp @ srcA^T : K=4096 ; 1-product
    gemm_tc<1><<<dim3(4,8,Hq*Bq), 256, 98304>>>(wpH, nullptr, srcAH, nullptr, nullptr, nullptr, o2H, nullptr,
        Dq, Dq, Bq, BT,Tq, 0,Tq, (long)Tq,TD, 0, 1.0f, 0, 0);
    // o3 = o2 @ dWo^T ; 1-product
    gemm_tc<1><<<dim3(16,64,1), 256, 98304>>>(o2H, nullptr, dWoTH, nullptr, dbo, o3, nullptr, nullptr,
        Dq, Dq, 1, 0,0, 0,0, 0,0, 0, 1.0f, 0, 0);
    // fused: trgf = (srcA+o3)+ln(...); ln2H = ln(trgf)
    resln2<<<BT, 256>>>(srcA, o3, g1, b1, g2, b2, trgf, ln2H);
    // h1 = gelu(ln2 @ fW1^T + fb1) ; ff = h1 @ fW2^T + fb2  -- fp16-acc 1-prod
    gemm_ff<<<dim3(80,64,1), 256, SMEMF>>>(ln2H, fW1TH, fb1, nullptr, h1H, Dq, FFq, 1);
    gemm_ff<<<dim3(16,64,1), 256, SMEMF>>>(h1H, fW2TH, fb2, ff, nullptr, FFq, Dq, 0);
    resln<<<BT, 256>>>(trgf, ff, g2, b2, out, nullptr, 1);
}

// round 15
// speedup vs baseline: 1.0622x; 1.0368x over previous
#include <cuda_runtime.h>
#include <cuda_fp16.h>
#include <math.h>
#include <stdint.h>

typedef __half hf;

#define Bq 8
#define Tq 1024
#define Dq 4096
#define Hq 4
#define HSq 1024
#define BT 8192
#define FFq 20480

// ----------------------------- scratch --------------------------------------
__device__ hf g_srcH[(size_t)BT*Dq], g_srcL[(size_t)BT*Dq];
__device__ hf g_attH[(size_t)BT*HSq];
__device__ hf g_WqTH[(size_t)Hq*HSq*Dq], g_WqTL[(size_t)Hq*HSq*Dq];
__device__ hf g_WkTH[(size_t)Hq*HSq*Dq], g_WkTL[(size_t)Hq*HSq*Dq];
__device__ hf g_WvTH[(size_t)Hq*HSq*Dq];
__device__ hf g_qH[(size_t)Hq*BT*HSq], g_qL[(size_t)Hq*BT*HSq];
__device__ hf g_kH[(size_t)Hq*BT*HSq], g_kL[(size_t)Hq*BT*HSq];
__device__ hf g_vH[(size_t)Hq*BT*HSq];
__device__ hf g_vTH[(size_t)Hq*BT*HSq];
__device__ float g_w[(size_t)Hq*Bq*Tq*Tq];
__device__ hf g_aH[(size_t)Hq*Bq*Tq*Tq];
__device__ float g_ocat[(size_t)BT*Dq];
__device__ float g_srcA[(size_t)BT*Dq];
__device__ hf g_srcAH[(size_t)BT*Dq];
__device__ hf g_dWpH[(size_t)Hq*HSq*Dq];          // dWp fp16, original [H][HS][D] layout
__device__ hf g_M2T[(size_t)Hq*Bq*Tq*Tq];          // [h][b][u][s]
__device__ float g_beta[(size_t)Hq*BT];            // [h][b*Tq+u]
__device__ hf g_o2H[(size_t)BT*Dq];
__device__ hf g_dWoTH[(size_t)Dq*Dq];
__device__ float g_o3[(size_t)BT*Dq];
__device__ float g_trgf[(size_t)BT*Dq];
__device__ hf g_ln2H[(size_t)BT*Dq];
__device__ hf g_fW1TH[(size_t)FFq*Dq];
__device__ hf g_h1H[(size_t)BT*FFq];
__device__ hf g_fW2TH[(size_t)Dq*FFq];
__device__ float g_ff[(size_t)BT*Dq];

// ----------------------------- helpers --------------------------------------
__device__ __forceinline__ uint32_t smem_u32(const void* p) {
    uint32_t a;
    asm("{ .reg .u64 t; cvta.to.shared.u64 t, %1; cvt.u32.u64 %0, t; }" : "=r"(a) : "l"(p));
    return a;
}
#define CPA16(dst, src) asm volatile("cp.async.cg.shared.global [%0], [%1], 16;" :: "r"((uint32_t)(dst)), "l"(src) : "memory")
#define CP_COMMIT()     asm volatile("cp.async.commit_group;" ::: "memory")
#define CP_WAIT1()      asm volatile("cp.async.wait_group 1;" ::: "memory")
#define LDSM4(r, a) asm volatile("ldmatrix.sync.aligned.m8n8.x4.shared.b16 {%0,%1,%2,%3}, [%4];" \
    : "=r"((r)[0]), "=r"((r)[1]), "=r"((r)[2]), "=r"((r)[3]) : "r"(a))
__device__ __forceinline__ void mma16816(float* d, const uint32_t* a, uint32_t b0, uint32_t b1) {
    asm volatile("mma.sync.aligned.m16n8k16.row.col.f32.f16.f16.f32 "
        "{%0,%1,%2,%3}, {%4,%5,%6,%7}, {%8,%9}, {%0,%1,%2,%3};"
        : "+f"(d[0]), "+f"(d[1]), "+f"(d[2]), "+f"(d[3])
        : "r"(a[0]), "r"(a[1]), "r"(a[2]), "r"(a[3]), "r"(b0), "r"(b1));
}
__device__ __forceinline__ void mma16816h(uint32_t* d, const uint32_t* a, uint32_t b0, uint32_t b1) {
    asm volatile("mma.sync.aligned.m16n8k16.row.col.f16.f16.f16.f16 "
        "{%0,%1}, {%2,%3,%4,%5}, {%6,%7}, {%0,%1};"
        : "+r"(d[0]), "+r"(d[1])
        : "r"(a[0]), "r"(a[1]), "r"(a[2]), "r"(a[3]), "r"(b0), "r"(b1));
}
__device__ __forceinline__ float gelu_exact(float x) { return 0.5f*x*(1.0f+erff(x*0.70710678118654752440f)); }
__device__ __forceinline__ void split_hf(float x, hf& h, hf& l) {
    h = __float2half(x); l = __float2half(x - __half2float(h));
}

#define SSTF  49152
#define SMEMF 98304

// ====== mma.sync split-fp16 GEMM: C = act(alpha*A@B^T + bias) ================
// fp32 accumulate. NPROD=3: Ah*Bh+Al*Bh+Ah*Bl (~2^-22 rel — REQUIRED for the
// attention score path: softmax shifts weights by exp(score abs err); every
// single fp16 rounding in q/k/scores costs ~0.47 abs). NPROD=1: ~4.9e-4,
// only for paths diluted by the final LN (decoder chain, v, AV, FF).
// bias indexed [col] after ptr += z1*sB1 + z2*sB2.
// causal: 0 none; 1 skip blocks above diagonal; 2 truncate K at diagonal.
// CTA tile 128x256, 8 warps (warp tile 64x64), K-chunk 64, cp.async 2-stage.
template<int NPROD>
__global__ void __launch_bounds__(256, 1)
gemm_tc(const hf* __restrict__ Ah, const hf* __restrict__ Al,
        const hf* __restrict__ Bh, const hf* __restrict__ Bl,
        const float* __restrict__ bias, float* __restrict__ C,
        hf* __restrict__ Ch, hf* __restrict__ Cl,
        int K, int ldc, int batch2, int aR1, int aR2, int bR1, int bR2,
        long sC1, long sC2, long sB1, long sB2, float alpha, int act, int causal)
{
    constexpr uint32_t B_OFF  = (NPROD >= 2) ? 32768u : 16384u;
    constexpr uint32_t BL_OFF = 65536u;
    constexpr uint32_t STAGE  = (NPROD == 3) ? 98304u : (NPROD == 2 ? 65536u : 49152u);

    if (causal == 1 && (int)blockIdx.x * 256 > (int)blockIdx.y * 128 + 127) return;
    extern __shared__ __align__(1024) char sm[];
    uint32_t sb = smem_u32(sm);
    int tid = threadIdx.x, wid = tid >> 5, lane = tid & 31;
    int z = blockIdx.z, z1 = z / batch2, z2 = z % batch2;
    long aOff = (long)z1*aR1 + (long)z2*aR2 + blockIdx.y*128;
    long bOff = (long)z1*bR1 + (long)z2*bR2 + blockIdx.x*256;
    int warp_m = (wid & 1) * 64, warp_n = (wid >> 1) * 64;

    float acc[4][8][4];
#pragma unroll
    for (int mt = 0; mt < 4; mt++)
#pragma unroll
        for (int nt = 0; nt < 8; nt++)
#pragma unroll
            for (int r = 0; r < 4; r++) acc[mt][nt][r] = 0.f;

    int nkt = K >> 6;
    if (causal == 2) { int lim = 2 * (int)blockIdx.y + 2; if (lim < nkt) nkt = lim; }

    auto load_stage = [&](int s, int kt) {
        uint32_t base = sb + s * STAGE;
        long kb = (long)kt * 64;
#pragma unroll
        for (int it = 0; it < 4; it++) {
            int idx = tid + it * 256;
            int r = idx >> 3, c = idx & 7;
            uint32_t off = (uint32_t)(r * 128 + ((c ^ (r & 7)) << 4));
            long gi = (aOff + r) * (long)K + kb + c * 8;
            CPA16(base + off, Ah + gi);
            if (NPROD >= 2) CPA16(base + 16384 + off, Al + gi);
        }
#pragma unroll
        for (int it = 0; it < 8; it++) {
            int idx = tid + it * 256;
            int r = idx >> 3, c = idx & 7;
            uint32_t off = (uint32_t)(r * 128 + ((c ^ (r & 7)) << 4));
            long gi = (bOff + r) * (long)K + kb + c * 8;
            CPA16(base + B_OFF + off, Bh + gi);
            if (NPROD == 3) CPA16(base + BL_OFF + off, Bl + gi);
        }
    };

    load_stage(0, 0);
    CP_COMMIT();

    for (int kt = 0; kt < nkt; kt++) {
        int s = kt & 1;
        if (kt + 1 < nkt) load_stage(s ^ 1, kt + 1);
        CP_COMMIT();
        CP_WAIT1();
        __syncthreads();

        uint32_t sA_h = sb + s * STAGE, sA_l = sA_h + 16384;
        uint32_t sB_h = sA_h + B_OFF, sB_l = sA_h + BL_OFF;
#pragma unroll
        for (int ks = 0; ks < 4; ks++) {
            uint32_t ah[4][4], al[4][4];
#pragma unroll
            for (int mt = 0; mt < 4; mt++) {
                int row = warp_m + mt * 16 + (lane & 15);
                int c16 = ks * 2 + (lane >> 4);
                uint32_t off = (uint32_t)(row * 128 + ((c16 ^ (row & 7)) << 4));
                LDSM4(ah[mt], sA_h + off);
                if (NPROD >= 2) LDSM4(al[mt], sA_l + off);
            }
#pragma unroll
            for (int p = 0; p < 4; p++) {
                int row = warp_n + p * 16 + ((lane >> 4) << 3) + (lane & 7);
                int c16 = ks * 2 + ((lane >> 3) & 1);
                uint32_t off = (uint32_t)(row * 128 + ((c16 ^ (row & 7)) << 4));
                uint32_t bh[4];
                LDSM4(bh, sB_h + off);
#pragma unroll
                for (int mt = 0; mt < 4; mt++) {
                    mma16816(acc[mt][2*p],   ah[mt], bh[0], bh[1]);
                    mma16816(acc[mt][2*p+1], ah[mt], bh[2], bh[3]);
                }
                if (NPROD >= 2) {
#pragma unroll
                    for (int mt = 0; mt < 4; mt++) {
                        mma16816(acc[mt][2*p],   al[mt], bh[0], bh[1]);
                        mma16816(acc[mt][2*p+1], al[mt], bh[2], bh[3]);
                    }
                }
                if (NPROD == 3) {
                    uint32_t bl[4];
                    LDSM4(bl, sB_l + off);
#pragma unroll
                    for (int mt = 0; mt < 4; mt++) {
                        mma16816(acc[mt][2*p],   ah[mt], bl[0], bl[1]);
                        mma16816(acc[mt][2*p+1], ah[mt], bl[2], bl[3]);
                    }
                }
            }
        }
        __syncthreads();
    }

    // ---- epilogue ----
    float* Cp = C ? C + z1*sC1 + z2*sC2 : nullptr;
    hf *Chp = Ch ? Ch + z1*sC1 + z2*sC2 : nullptr;
    hf *Clp = Cl ? Cl + z1*sC1 + z2*sC2 : nullptr;
    const float* bp = bias ? bias + z1*sB1 + z2*sB2 : nullptr;
    int rowBase = blockIdx.y*128 + warp_m + (lane >> 2);
    int colBase = blockIdx.x*256 + warp_n + (lane & 3) * 2;
#pragma unroll
    for (int mt = 0; mt < 4; mt++) {
#pragma unroll
        for (int nt = 0; nt < 8; nt++) {
#pragma unroll
            for (int hh = 0; hh < 2; hh++) {
                int row = rowBase + mt * 16 + hh * 8;
                int col = colBase + nt * 8;
                float x0 = acc[mt][nt][hh*2]     * alpha;
                float x1 = acc[mt][nt][hh*2 + 1] * alpha;
                if (bp) { x0 += bp[col]; x1 += bp[col + 1]; }
                if (act) { x0 = gelu_exact(x0); x1 = gelu_exact(x1); }
                long o = (long)row * ldc + col;
                if (Cp) *(float2*)(Cp + o) = make_float2(x0, x1);
                if (Chp) {
                    hf h0, l0, h1, l1;
                    split_hf(x0, h0, l0); split_hf(x1, h1, l1);
                    *(__half2*)(Chp + o) = __halves2half2(h0, h1);
                    if (Clp) *(__half2*)(Clp + o) = __halves2half2(l0, l1);
                }
            }
        }
    }
}

// ====== FF GEMM: fp16 x fp16, fp16 accumulate, 1-product ====================
__global__ void __launch_bounds__(256, 2)
gemm_ff(const hf* __restrict__ A, const hf* __restrict__ B,
        const float* __restrict__ bias, float* __restrict__ C, hf* __restrict__ Ch,
        int K, int ldc, int act)
{
    extern __shared__ __align__(1024) char sm[];
    uint32_t sb = smem_u32(sm);
    int tid = threadIdx.x, wid = tid >> 5, lane = tid & 31;
    long aOff = blockIdx.y * 128;
    long bOff = blockIdx.x * 256;
    int warp_m = (wid & 1) * 64, warp_n = (wid >> 1) * 64;

    uint32_t hacc[4][8][2];
#pragma unroll
    for (int mt = 0; mt < 4; mt++)
#pragma unroll
        for (int nt = 0; nt < 8; nt++) { hacc[mt][nt][0] = 0u; hacc[mt][nt][1] = 0u; }

    int nkt = K >> 6;
    auto load_stage = [&](int s, int kt) {
        uint32_t base = sb + s * SSTF;
        long kb = (long)kt * 64;
#pragma unroll
        for (int it = 0; it < 4; it++) {
            int idx = tid + it * 256;
            int r = idx >> 3, c = idx & 7;
            uint32_t off = (uint32_t)(r * 128 + ((c ^ (r & 7)) << 4));
            CPA16(base + off, A + (aOff + r) * (long)K + kb + c * 8);
        }
#pragma unroll
        for (int it = 0; it < 8; it++) {
            int idx = tid + it * 256;
            int r = idx >> 3, c = idx & 7;
            uint32_t off = (uint32_t)(r * 128 + ((c ^ (r & 7)) << 4));
            CPA16(base + 16384 + off, B + (bOff + r) * (long)K + kb + c * 8);
        }
    };

    load_stage(0, 0);
    CP_COMMIT();

    for (int kt = 0; kt < nkt; kt++) {
        int s = kt & 1;
        if (kt + 1 < nkt) load_stage(s ^ 1, kt + 1);
        CP_COMMIT();
        CP_WAIT1();
        __syncthreads();

        uint32_t sA = sb + s * SSTF, sB = sA + 16384;
#pragma unroll
        for (int ks = 0; ks < 4; ks++) {
            uint32_t ah[4][4];
#pragma unroll
            for (int mt = 0; mt < 4; mt++) {
                int row = warp_m + mt * 16 + (lane & 15);
                int c16 = ks * 2 + (lane >> 4);
                uint32_t off = (uint32_t)(row * 128 + ((c16 ^ (row & 7)) << 4));
                LDSM4(ah[mt], sA + off);
            }
#pragma unroll
            for (int p = 0; p < 4; p++) {
                int row = warp_n + p * 16 + ((lane >> 4) << 3) + (lane & 7);
                int c16 = ks * 2 + ((lane >> 3) & 1);
                uint32_t off = (uint32_t)(row * 128 + ((c16 ^ (row & 7)) << 4));
                uint32_t bh[4];
                LDSM4(bh, sB + off);
#pragma unroll
                for (int mt = 0; mt < 4; mt++) {
                    mma16816h(hacc[mt][2*p],   ah[mt], bh[0], bh[1]);
                    mma16816h(hacc[mt][2*p+1], ah[mt], bh[2], bh[3]);
                }
            }
        }
        __syncthreads();
    }

    int rowBase = blockIdx.y*128 + warp_m + (lane >> 2);
    int colBase = blockIdx.x*256 + warp_n + (lane & 3) * 2;
#pragma unroll
    for (int mt = 0; mt < 4; mt++) {
#pragma unroll
        for (int nt = 0; nt < 8; nt++) {
#pragma unroll
            for (int hh = 0; hh < 2; hh++) {
                int row = rowBase + mt * 16 + hh * 8;
                int col = colBase + nt * 8;
                __half2 hv = *(__half2*)&hacc[mt][nt][hh];
                float x0 = __low2float(hv), x1 = __high2float(hv);
                if (bias) { x0 += bias[col]; x1 += bias[col + 1]; }
                if (act) { x0 = gelu_exact(x0); x1 = gelu_exact(x1); }
                long o = (long)row * ldc + col;
                if (C) *(float2*)(C + o) = make_float2(x0, x1);
                if (Ch) *(__half2*)(Ch + o) = __halves2half2(__float2half(x0), __float2half(x1));
            }
        }
    }
}

// ---------------- fp32 -> (hi,lo) fp16 --------------------------------------
__global__ void conv_hl(const float4* __restrict__ x, hf* __restrict__ h, hf* __restrict__ l) {
    long i = (long)blockIdx.x*256 + threadIdx.x;
    float4 v = x[i];
    hf h0,l0,h1,l1,h2,l2,h3,l3;
    split_hf(v.x,h0,l0); split_hf(v.y,h1,l1); split_hf(v.z,h2,l2); split_hf(v.w,h3,l3);
    __half2* hp = (__half2*)(h + 4*i);
    hp[0]=__halves2half2(h0,h1); hp[1]=__halves2half2(h2,h3);
    if (l) {
        __half2* lp = (__half2*)(l + 4*i);
        lp[0]=__halves2half2(l0,l1); lp[1]=__halves2half2(l2,l3);
    }
}

// ------------- transpose+split: in[z][R][Cc] -> out[z][Cc][R] (fp32 in) ------
__global__ void tconv(const float* __restrict__ in, hf* __restrict__ oh, hf* __restrict__ ol, int R, int Cc) {
    __shared__ float t[32][33];
    long base = (long)blockIdx.z * R * Cc;
    int c0 = blockIdx.x*32, r0 = blockIdx.y*32;
#pragma unroll
    for (int i = 0; i < 4; i++)
        t[threadIdx.y + i*8][threadIdx.x] = in[base + (long)(r0 + threadIdx.y + i*8)*Cc + c0 + threadIdx.x];
    __syncthreads();
#pragma unroll
    for (int i = 0; i < 4; i++) {
        int c = c0 + threadIdx.y + i*8, r = r0 + threadIdx.x;
        hf h, l; split_hf(t[threadIdx.x][threadIdx.y + i*8], h, l);
        long o = base + (long)c*R + r;
        oh[o] = h;
        if (ol) ol[o] = l;
    }
}

// ------------- transpose (fp16 in -> fp16 out): in[z][R][Cc] -> out[z][Cc][R]
__global__ void tconv_h(const hf* __restrict__ in, hf* __restrict__ oh, int R, int Cc) {
    __shared__ hf t[32][34];
    long base = (long)blockIdx.z * R * Cc;
    int c0 = blockIdx.x*32, r0 = blockIdx.y*32;
#pragma unroll
    for (int i = 0; i < 4; i++)
        t[threadIdx.y + i*8][threadIdx.x] = in[base + (long)(r0 + threadIdx.y + i*8)*Cc + c0 + threadIdx.x];
    __syncthreads();
#pragma unroll
    for (int i = 0; i < 4; i++) {
        int c = c0 + threadIdx.y + i*8, r = r0 + threadIdx.x;
        oh[base + (long)c*R + r] = t[threadIdx.x][threadIdx.y + i*8];
    }
}

// ------------------ causal softmax -> fp16 (hi only) -------------------------
__global__ void softmax_causal(const float* __restrict__ w, hf* __restrict__ aH) {
    long row = blockIdx.x;
    int t = (int)(row % Tq), tid = threadIdx.x;
    const float* p = w + row*(long)Tq;
    __shared__ float red[256];
    float vals[4], vmax = -1e30f;
#pragma unroll
    for (int i = 0; i < 4; i++) {
        int j = tid + i*256; float x = p[j]; vals[i] = x;
        if (j <= t && x > vmax) vmax = x;
    }
    red[tid] = vmax; __syncthreads();
    for (int s = 128; s > 0; s >>= 1) { if (tid < s) red[tid] = fmaxf(red[tid], red[tid+s]); __syncthreads(); }
    vmax = red[0]; __syncthreads();
    float sum = 0.f;
#pragma unroll
    for (int i = 0; i < 4; i++) {
        int j = tid + i*256;
        float e = (j <= t) ? expf(vals[i] - vmax) : 0.f;
        vals[i] = e; sum += e;
    }
    red[tid] = sum; __syncthreads();
    for (int s = 128; s > 0; s >>= 1) { if (tid < s) red[tid] += red[tid+s]; __syncthreads(); }
    float inv = 1.f / red[0];
#pragma unroll
    for (int i = 0; i < 4; i++)
        aH[row*(long)Tq + tid + i*256] = __float2half(vals[i]*inv);
}

// --------- beta[h][row] = dot(dbp[h,:], srcA[row,:])  (exact dbp handling) ---
__global__ void beta_k(const float* __restrict__ srcA, const float* __restrict__ dbp,
                       float* __restrict__ beta) {
    long row = blockIdx.x;
    int tid = threadIdx.x;
    const float* p = srcA + row*(long)Dq;
    __shared__ float red[256];
    float s[Hq] = {0.f, 0.f, 0.f, 0.f};
    for (int i = tid; i < Dq; i += 256) {
        float x = p[i];
        s[0] += x * dbp[i];
        s[1] += x * dbp[Dq + i];
        s[2] += x * dbp[2*Dq + i];
        s[3] += x * dbp[3*Dq + i];
    }
#pragma unroll
    for (int h = 0; h < Hq; h++) {
        red[tid] = s[h]; __syncthreads();
        for (int st = 128; st > 0; st >>= 1) { if (tid < st) red[tid] += red[tid+st]; __syncthreads(); }
        if (tid == 0) beta[(long)h*BT + row] = red[0];
        __syncthreads();
    }
}

// --- residual+LN: t = x(+y); out = ln_only ? ln(t) : t+ln(t); fp16 out opt ---
__global__ void resln(const float* __restrict__ x, const float* __restrict__ y,
                      const float* __restrict__ g, const float* __restrict__ b,
                      float* __restrict__ out, hf* __restrict__ oh, int ln_only) {
    long row = blockIdx.x;
    int tid = threadIdx.x;
    const float* px = x + row*(long)Dq;
    const float* py = y ? y + row*(long)Dq : nullptr;
    __shared__ float sh[Dq];
    __shared__ float red[256];
    float ls = 0.f;
    for (int i = tid; i < Dq; i += 256) { float t = px[i] + (py ? py[i] : 0.f); sh[i] = t; ls += t; }
    red[tid] = ls; __syncthreads();
    for (int s = 128; s > 0; s >>= 1) { if (tid < s) red[tid] += red[tid+s]; __syncthreads(); }
    float mean = red[0] * (1.0f/Dq); __syncthreads();
    float lv = 0.f;
    for (int i = tid; i < Dq; i += 256) { float d = sh[i]-mean; lv += d*d; }
    red[tid] = lv; __syncthreads();
    for (int s = 128; s > 0; s >>= 1) { if (tid < s) red[tid] += red[tid+s]; __syncthreads(); }
    float rstd = rsqrtf(red[0]*(1.0f/Dq) + 1e-5f);
    for (int i = tid; i < Dq; i += 256) {
        float t = sh[i];
        float l = (t - mean)*rstd*g[i] + b[i];
        float o = ln_only ? l : t + l;
        long oi = row*(long)Dq + i;
        if (out) out[oi] = o;
        if (oh) oh[oi] = __float2half(o);
    }
}

// --- fused double-LN: t = x+y; trgf = t+ln(t,g1,b1); ln2h = ln(trgf,g2,b2) ---
__global__ void resln2(const float* __restrict__ x, const float* __restrict__ y,
                       const float* __restrict__ g1, const float* __restrict__ b1,
                       const float* __restrict__ g2, const float* __restrict__ b2,
                       float* __restrict__ trgf, hf* __restrict__ ln2h) {
    long row = blockIdx.x;
    int tid = threadIdx.x;
    const float* px = x + row*(long)Dq;
    const float* py = y + row*(long)Dq;
    __shared__ float sh[Dq];
    __shared__ float red[256];
    float ls = 0.f;
    for (int i = tid; i < Dq; i += 256) { float t = px[i] + py[i]; sh[i] = t; ls += t; }
    red[tid] = ls; __syncthreads();
    for (int s = 128; s > 0; s >>= 1) { if (tid < s) red[tid] += red[tid+s]; __syncthreads(); }
    float mean = red[0] * (1.0f/Dq); __syncthreads();
    float lv = 0.f;
    for (int i = tid; i < Dq; i += 256) { float d = sh[i]-mean; lv += d*d; }
    red[tid] = lv; __syncthreads();
    for (int s = 128; s > 0; s >>= 1) { if (tid < s) red[tid] += red[tid+s]; __syncthreads(); }
    float rstd = rsqrtf(red[0]*(1.0f/Dq) + 1e-5f);
    __syncthreads();
    float ls2 = 0.f;
    for (int i = tid; i < Dq; i += 256) {
        float t = sh[i];
        float o = t + (t - mean)*rstd*g1[i] + b1[i];
        sh[i] = o; ls2 += o;
        trgf[row*(long)Dq + i] = o;
    }
    red[tid] = ls2; __syncthreads();
    for (int s = 128; s > 0; s >>= 1) { if (tid < s) red[tid] += red[tid+s]; __syncthreads(); }
    float mean2 = red[0] * (1.0f/Dq); __syncthreads();
    float lv2 = 0.f;
    for (int i = tid; i < Dq; i += 256) { float d = sh[i]-mean2; lv2 += d*d; }
    red[tid] = lv2; __syncthreads();
    for (int s = 128; s > 0; s >>= 1) { if (tid < s) red[tid] += red[tid+s]; __syncthreads(); }
    float rstd2 = rsqrtf(red[0]*(1.0f/Dq) + 1e-5f);
    for (int i = tid; i < Dq; i += 256)
        ln2h[row*(long)Dq + i] = __float2half((sh[i] - mean2)*rstd2*g2[i] + b2[i]);
}

// -----------------------------------------------------------------------------
extern "C" void kernel_launch(void* const* d_in, const int* in_sizes, int n_in,
                              void* d_out, int out_size)
{
    const float* src=(const float*)d_in[0]; const float* att=(const float*)d_in[1];
    const float* mWq=(const float*)d_in[2]; const float* mbq=(const float*)d_in[3];
    const float* mWk=(const float*)d_in[4]; const float* mbk=(const float*)d_in[5];
    const float* mWv=(const float*)d_in[6]; const float* dWp=(const float*)d_in[7];
    const float* dbp=(const float*)d_in[8]; const float* dWo=(const float*)d_in[9];
    const float* dbo=(const float*)d_in[10]; const float* fW1=(const float*)d_in[11];
    const float* fb1=(const float*)d_in[12]; const float* fW2=(const float*)d_in[13];
    const float* fb2=(const float*)d_in[14]; const float* g1=(const float*)d_in[15];
    const float* b1=(const float*)d_in[16]; const float* g2=(const float*)d_in[17];
    const float* b2=(const float*)d_in[18];
    float* out = (float*)d_out;

#define SYM(T,p,s) T p; cudaGetSymbolAddress((void**)&p, s)
    SYM(hf*,srcH,g_srcH); SYM(hf*,srcL,g_srcL); SYM(hf*,attH,g_attH);
    SYM(hf*,WqTH,g_WqTH); SYM(hf*,WqTL,g_WqTL); SYM(hf*,WkTH,g_WkTH); SYM(hf*,WkTL,g_WkTL);
    SYM(hf*,WvTH,g_WvTH);
    SYM(hf*,qH,g_qH); SYM(hf*,qL,g_qL); SYM(hf*,kH,g_kH); SYM(hf*,kL,g_kL);
    SYM(hf*,vH,g_vH); SYM(hf*,vTH,g_vTH);
    SYM(float*,w,g_w); SYM(hf*,aH,g_aH);
    SYM(float*,ocat,g_ocat); SYM(float*,srcA,g_srcA); SYM(hf*,srcAH,g_srcAH);
    SYM(hf*,dWpH,g_dWpH); SYM(hf*,M2T,g_M2T); SYM(float*,beta,g_beta);
    SYM(hf*,o2H,g_o2H); SYM(hf*,dWoTH,g_dWoTH);
    SYM(float*,o3,g_o3); SYM(float*,trgf,g_trgf); SYM(hf*,ln2H,g_ln2H);
    SYM(hf*,fW1TH,g_fW1TH); SYM(hf*,h1H,g_h1H);
    SYM(hf*,fW2TH,g_fW2TH); SYM(float*,ff,g_ff);

    cudaFuncSetAttribute(gemm_tc<1>, cudaFuncAttributeMaxDynamicSharedMemorySize, 98304);
    cudaFuncSetAttribute(gemm_tc<3>, cudaFuncAttributeMaxDynamicSharedMemorySize, 196608);
    cudaFuncSetAttribute(gemm_ff,    cudaFuncAttributeMaxDynamicSharedMemorySize, SMEMF);
    dim3 tb(32, 8);
    const long TT=(long)Tq*Tq, TD=(long)Tq*Dq, BTD=(long)BT*Dq, BTHS=(long)BT*HSq, BTT=(long)Bq*Tq*Tq;

    // operand prep (dWp: straight fp32->fp16 convert, original layout)
    conv_hl<<<BTD/1024, 256>>>((const float4*)src, srcH, srcL);
    conv_hl<<<BTHS/1024, 256>>>((const float4*)att, attH, nullptr);
    conv_hl<<<(Hq*HSq*Dq)/1024, 256>>>((const float4*)dWp, dWpH, nullptr);
    tconv<<<dim3(HSq/32, Dq/32, Hq), tb>>>(mWq, WqTH, WqTL, Dq, HSq);
    tconv<<<dim3(HSq/32, Dq/32, Hq), tb>>>(mWk, WkTH, WkTL, Dq, HSq);
    tconv<<<dim3(HSq/32, Dq/32, Hq), tb>>>(mWv, WvTH, nullptr, Dq, HSq);
    tconv<<<dim3(Dq/32, Dq/32, 1), tb>>>(dWo, dWoTH, nullptr, Dq, Dq);
    tconv<<<dim3(FFq/32, Dq/32, 1), tb>>>(fW1, fW1TH, nullptr, Dq, FFq);
    tconv<<<dim3(Dq/32, FFq/32, 1), tb>>>(fW2, fW2TH, nullptr, FFq, Dq);

    // q,k: 3-product (score abs error must be <<1 for softmax), v: 1-product
    gemm_tc<3><<<dim3(4,64,Hq), 256, 196608>>>(srcH, srcL, WqTH, WqTL, mbq, nullptr, qH, qL,
        Dq, HSq, 1, 0,0, HSq,0, BTHS,0, HSq,0, 1.0f, 0, 0);
    gemm_tc<3><<<dim3(4,64,Hq), 256, 196608>>>(srcH, srcL, WkTH, WkTL, mbk, nullptr, kH, kL,
        Dq, HSq, 1, 0,0, HSq,0, BTHS,0, HSq,0, 1.0f, 0, 0);
    gemm_tc<1><<<dim3(4,64,Hq), 256, 98304>>>(srcH, nullptr, WvTH, nullptr, nullptr, nullptr, vH, nullptr,
        Dq, HSq, 1, 0,0, HSq,0, BTHS,0, 0,0, 1.0f, 0, 0);
    tconv_h<<<dim3(HSq/32, Tq/32, Hq*Bq), tb>>>(vH, vTH, Tq, HSq);
    // scores: 3-product, causal block-skip
    gemm_tc<3><<<dim3(4,8,Hq*Bq), 256, 196608>>>(qH, qL, kH, kL, nullptr, w, nullptr, nullptr,
        HSq, Tq, Bq, BT,Tq, BT,Tq, BTT,TT, 0,0, 32.0f, 0, 1);
    softmax_causal<<<Hq*Bq*Tq, 256>>>(w, aH);
    // o = a @ vT^T : 1-product, K truncated at diagonal
    gemm_tc<1><<<dim3(4,8,Hq*Bq), 256, 98304>>>(aH, nullptr, vTH, nullptr, nullptr, ocat, nullptr, nullptr,
        Tq, Dq, Bq, Bq*Tq,Tq, Bq*HSq,HSq, (long)HSq,TD, 0,0, 1.0f, 0, 2);
    resln<<<BT, 256>>>(src, ocat, g1, b1, srcA, srcAH, 0);
    // --- reassociated decoder attention (saves wp = 137 GMAC) ---
    // M2T[h,b][u,s] = srcA[b] @ dWp[h]^T : 1-product, dWp in ORIGINAL layout
    gemm_tc<1><<<dim3(4,8,Hq*Bq), 256, 98304>>>(srcAH, nullptr, dWpH, nullptr, nullptr, nullptr, M2T, nullptr,
        Dq, Tq, Bq, 0,Tq, HSq,0, (long)Bq*TT,TT, 0,0, 1.0f, 0, 0);
    // beta[h][b*Tq+u] = dot(dbp[h], srcA[b,u,:])  (exact dbp handling)
    beta_k<<<BT, 256>>>(srcA, dbp, beta);
    // o2[b,t, h*Tq+u] = att[b] @ M2T[h,b]^T + beta : K=1024, 1-product
    gemm_tc<1><<<dim3(4,8,Hq*Bq), 256, 98304>>>(attH, nullptr, M2T, nullptr, beta, nullptr, o2H, nullptr,
        HSq, Dq, Bq, 0,Tq, Bq*Tq,Tq, (long)Tq,TD, (long)BT,(long)Tq, 1.0f, 0, 0);
    // o3 = o2 @ dWo^T ; 1-product
    gemm_tc<1><<<dim3(16,64,1), 256, 98304>>>(o2H, nullptr, dWoTH, nullptr, dbo, o3, nullptr, nullptr,
        Dq, Dq, 1, 0,0, 0,0, 0,0, 0,0, 1.0f, 0, 0);
    // fused: trgf = (srcA+o3)+ln(...); ln2H = ln(trgf)
    resln2<<<BT, 256>>>(srcA, o3, g1, b1, g2, b2, trgf, ln2H);
    // h1 = gelu(ln2 @ fW1^T + fb1) ; ff = h1 @ fW2^T + fb2  -- fp16-acc 1-prod
    gemm_ff<<<dim3(80,64,1), 256, SMEMF>>>(ln2H, fW1TH, fb1, nullptr, h1H, Dq, FFq, 1);
    gemm_ff<<<dim3(16,64,1), 256, SMEMF>>>(h1H, fW2TH, fb2, ff, nullptr, FFq, Dq, 0);
    resln<<<BT, 256>>>(trgf, ff, g2, b2, out, nullptr, 1);
}

// round 16
// speedup vs baseline: 1.0798x; 1.0167x over previous
#include <cuda_runtime.h>
#include <cuda_fp16.h>
#include <math.h>
#include <stdint.h>

typedef __half hf;

#define Bq 8
#define Tq 1024
#define Dq 4096
#define Hq 4
#define HSq 1024
#define BT 8192
#define FFq 20480

// ----------------------------- scratch --------------------------------------
__device__ hf g_srcH[(size_t)BT*Dq], g_srcL[(size_t)BT*Dq];
__device__ hf g_attH[(size_t)BT*HSq];
__device__ hf g_WqTH[(size_t)Hq*HSq*Dq], g_WqTL[(size_t)Hq*HSq*Dq];
__device__ hf g_WkTH[(size_t)Hq*HSq*Dq], g_WkTL[(size_t)Hq*HSq*Dq];
__device__ hf g_WvTH[(size_t)Hq*HSq*Dq];
__device__ hf g_qH[(size_t)Hq*BT*HSq], g_qL[(size_t)Hq*BT*HSq];
__device__ hf g_kH[(size_t)Hq*BT*HSq], g_kL[(size_t)Hq*BT*HSq];
__device__ hf g_vH[(size_t)Hq*BT*HSq];
__device__ hf g_vTH[(size_t)Hq*BT*HSq];
__device__ float g_w[(size_t)Hq*Bq*Tq*Tq];
__device__ hf g_aH[(size_t)Hq*Bq*Tq*Tq];
__device__ float g_ocat[(size_t)BT*Dq];
__device__ float g_srcA[(size_t)BT*Dq];
__device__ hf g_srcAH[(size_t)BT*Dq];
__device__ hf g_dWpH[(size_t)Hq*HSq*Dq];
__device__ hf g_M2T[(size_t)Hq*Bq*Tq*Tq];
__device__ float g_beta[(size_t)Hq*BT];
__device__ hf g_o2H[(size_t)BT*Dq];
__device__ hf g_dWoTH[(size_t)Dq*Dq];
__device__ float g_o3[(size_t)BT*Dq];
__device__ float g_trgf[(size_t)BT*Dq];
__device__ hf g_ln2H[(size_t)BT*Dq];
__device__ hf g_fW1TH[(size_t)FFq*Dq];
__device__ hf g_h1H[(size_t)BT*FFq];
__device__ hf g_fW2TH[(size_t)Dq*FFq];
__device__ float g_ff[(size_t)BT*Dq];

// ----------------------------- helpers --------------------------------------
__device__ __forceinline__ uint32_t smem_u32(const void* p) {
    uint32_t a;
    asm("{ .reg .u64 t; cvta.to.shared.u64 t, %1; cvt.u32.u64 %0, t; }" : "=r"(a) : "l"(p));
    return a;
}
#define CPA16(dst, src) asm volatile("cp.async.cg.shared.global [%0], [%1], 16;" :: "r"((uint32_t)(dst)), "l"(src) : "memory")
#define CP_COMMIT()     asm volatile("cp.async.commit_group;" ::: "memory")
#define CP_WAIT1()      asm volatile("cp.async.wait_group 1;" ::: "memory")
#define LDSM4(r, a) asm volatile("ldmatrix.sync.aligned.m8n8.x4.shared.b16 {%0,%1,%2,%3}, [%4];" \
    : "=r"((r)[0]), "=r"((r)[1]), "=r"((r)[2]), "=r"((r)[3]) : "r"(a))
__device__ __forceinline__ void mma16816(float* d, const uint32_t* a, uint32_t b0, uint32_t b1) {
    asm volatile("mma.sync.aligned.m16n8k16.row.col.f32.f16.f16.f32 "
        "{%0,%1,%2,%3}, {%4,%5,%6,%7}, {%8,%9}, {%0,%1,%2,%3};"
        : "+f"(d[0]), "+f"(d[1]), "+f"(d[2]), "+f"(d[3])
        : "r"(a[0]), "r"(a[1]), "r"(a[2]), "r"(a[3]), "r"(b0), "r"(b1));
}
__device__ __forceinline__ void mma16816h(uint32_t* d, const uint32_t* a, uint32_t b0, uint32_t b1) {
    asm volatile("mma.sync.aligned.m16n8k16.row.col.f16.f16.f16.f16 "
        "{%0,%1}, {%2,%3,%4,%5}, {%6,%7}, {%0,%1};"
        : "+r"(d[0]), "+r"(d[1])
        : "r"(a[0]), "r"(a[1]), "r"(a[2]), "r"(a[3]), "r"(b0), "r"(b1));
}
__device__ __forceinline__ float gelu_exact(float x) { return 0.5f*x*(1.0f+erff(x*0.70710678118654752440f)); }
__device__ __forceinline__ void split_hf(float x, hf& h, hf& l) {
    h = __float2half(x); l = __float2half(x - __half2float(h));
}

#define SSTF  49152
#define SMEMF 98304

// ====== mma.sync split-fp16 GEMM: C = act(alpha*A@B^T + bias) ================
// fp32 accumulate. NPROD=3: Ah*Bh+Al*Bh+Ah*Bl (~2^-22 rel — REQUIRED for the
// attention score path: softmax shifts weights by exp(score abs err); any
// single fp16 rounding in q/k/scores costs ~0.5-0.8 abs score error).
// NPROD=1: ~4.9e-4, only for paths diluted by the final LN.
// causal: 0 none; 1 skip blocks above diagonal; 2 truncate K at diagonal.
// CTA tile 128x256, 8 warps (warp tile 64x64), K-chunk 64, cp.async 2-stage.
template<int NPROD>
__global__ void __launch_bounds__(256, 1)
gemm_tc(const hf* __restrict__ Ah, const hf* __restrict__ Al,
        const hf* __restrict__ Bh, const hf* __restrict__ Bl,
        const float* __restrict__ bias, float* __restrict__ C,
        hf* __restrict__ Ch, hf* __restrict__ Cl,
        int K, int ldc, int batch2, int aR1, int aR2, int bR1, int bR2,
        long sC1, long sC2, long sB1, long sB2, float alpha, int act, int causal)
{
    constexpr uint32_t B_OFF  = (NPROD >= 2) ? 32768u : 16384u;
    constexpr uint32_t BL_OFF = 65536u;
    constexpr uint32_t STAGE  = (NPROD == 3) ? 98304u : (NPROD == 2 ? 65536u : 49152u);

    if (causal == 1 && (int)blockIdx.x * 256 > (int)blockIdx.y * 128 + 127) return;
    extern __shared__ __align__(1024) char sm[];
    uint32_t sb = smem_u32(sm);
    int tid = threadIdx.x, wid = tid >> 5, lane = tid & 31;
    int z = blockIdx.z, z1 = z / batch2, z2 = z % batch2;
    long aOff = (long)z1*aR1 + (long)z2*aR2 + blockIdx.y*128;
    long bOff = (long)z1*bR1 + (long)z2*bR2 + blockIdx.x*256;
    int warp_m = (wid & 1) * 64, warp_n = (wid >> 1) * 64;

    float acc[4][8][4];
#pragma unroll
    for (int mt = 0; mt < 4; mt++)
#pragma unroll
        for (int nt = 0; nt < 8; nt++)
#pragma unroll
            for (int r = 0; r < 4; r++) acc[mt][nt][r] = 0.f;

    int nkt = K >> 6;
    if (causal == 2) { int lim = 2 * (int)blockIdx.y + 2; if (lim < nkt) nkt = lim; }

    auto load_stage = [&](int s, int kt) {
        uint32_t base = sb + s * STAGE;
        long kb = (long)kt * 64;
#pragma unroll
        for (int it = 0; it < 4; it++) {
            int idx = tid + it * 256;
            int r = idx >> 3, c = idx & 7;
            uint32_t off = (uint32_t)(r * 128 + ((c ^ (r & 7)) << 4));
            long gi = (aOff + r) * (long)K + kb + c * 8;
            CPA16(base + off, Ah + gi);
            if (NPROD >= 2) CPA16(base + 16384 + off, Al + gi);
        }
#pragma unroll
        for (int it = 0; it < 8; it++) {
            int idx = tid + it * 256;
            int r = idx >> 3, c = idx & 7;
            uint32_t off = (uint32_t)(r * 128 + ((c ^ (r & 7)) << 4));
            long gi = (bOff + r) * (long)K + kb + c * 8;
            CPA16(base + B_OFF + off, Bh + gi);
            if (NPROD == 3) CPA16(base + BL_OFF + off, Bl + gi);
        }
    };

    load_stage(0, 0);
    CP_COMMIT();

    for (int kt = 0; kt < nkt; kt++) {
        int s = kt & 1;
        if (kt + 1 < nkt) load_stage(s ^ 1, kt + 1);
        CP_COMMIT();
        CP_WAIT1();
        __syncthreads();

        uint32_t sA_h = sb + s * STAGE, sA_l = sA_h + 16384;
        uint32_t sB_h = sA_h + B_OFF, sB_l = sA_h + BL_OFF;
#pragma unroll
        for (int ks = 0; ks < 4; ks++) {
            uint32_t ah[4][4], al[4][4];
#pragma unroll
            for (int mt = 0; mt < 4; mt++) {
                int row = warp_m + mt * 16 + (lane & 15);
                int c16 = ks * 2 + (lane >> 4);
                uint32_t off = (uint32_t)(row * 128 + ((c16 ^ (row & 7)) << 4));
                LDSM4(ah[mt], sA_h + off);
                if (NPROD >= 2) LDSM4(al[mt], sA_l + off);
            }
#pragma unroll
            for (int p = 0; p < 4; p++) {
                int row = warp_n + p * 16 + ((lane >> 4) << 3) + (lane & 7);
                int c16 = ks * 2 + ((lane >> 3) & 1);
                uint32_t off = (uint32_t)(row * 128 + ((c16 ^ (row & 7)) << 4));
                uint32_t bh[4];
                LDSM4(bh, sB_h + off);
#pragma unroll
                for (int mt = 0; mt < 4; mt++) {
                    mma16816(acc[mt][2*p],   ah[mt], bh[0], bh[1]);
                    mma16816(acc[mt][2*p+1], ah[mt], bh[2], bh[3]);
                }
                if (NPROD >= 2) {
#pragma unroll
                    for (int mt = 0; mt < 4; mt++) {
                        mma16816(acc[mt][2*p],   al[mt], bh[0], bh[1]);
                        mma16816(acc[mt][2*p+1], al[mt], bh[2], bh[3]);
                    }
                }
                if (NPROD == 3) {
                    uint32_t bl[4];
                    LDSM4(bl, sB_l + off);
#pragma unroll
                    for (int mt = 0; mt < 4; mt++) {
                        mma16816(acc[mt][2*p],   ah[mt], bl[0], bl[1]);
                        mma16816(acc[mt][2*p+1], ah[mt], bl[2], bl[3]);
                    }
                }
            }
        }
        __syncthreads();
    }

    // ---- epilogue ----
    float* Cp = C ? C + z1*sC1 + z2*sC2 : nullptr;
    hf *Chp = Ch ? Ch + z1*sC1 + z2*sC2 : nullptr;
    hf *Clp = Cl ? Cl + z1*sC1 + z2*sC2 : nullptr;
    const float* bp = bias ? bias + z1*sB1 + z2*sB2 : nullptr;
    int rowBase = blockIdx.y*128 + warp_m + (lane >> 2);
    int colBase = blockIdx.x*256 + warp_n + (lane & 3) * 2;
#pragma unroll
    for (int mt = 0; mt < 4; mt++) {
#pragma unroll
        for (int nt = 0; nt < 8; nt++) {
#pragma unroll
            for (int hh = 0; hh < 2; hh++) {
                int row = rowBase + mt * 16 + hh * 8;
                int col = colBase + nt * 8;
                float x0 = acc[mt][nt][hh*2]     * alpha;
                float x1 = acc[mt][nt][hh*2 + 1] * alpha;
                if (bp) { x0 += bp[col]; x1 += bp[col + 1]; }
                if (act) { x0 = gelu_exact(x0); x1 = gelu_exact(x1); }
                long o = (long)row * ldc + col;
                if (Cp) *(float2*)(Cp + o) = make_float2(x0, x1);
                if (Chp) {
                    hf h0, l0, h1, l1;
                    split_hf(x0, h0, l0); split_hf(x1, h1, l1);
                    *(__half2*)(Chp + o) = __halves2half2(h0, h1);
                    if (Clp) *(__half2*)(Clp + o) = __halves2half2(l0, l1);
                }
            }
        }
    }
}

// ====== FF GEMM: fp16 x fp16, fp16 accumulate, 1-product ====================
__global__ void __launch_bounds__(256, 2)
gemm_ff(const hf* __restrict__ A, const hf* __restrict__ B,
        const float* __restrict__ bias, float* __restrict__ C, hf* __restrict__ Ch,
        int K, int ldc, int act)
{
    extern __shared__ __align__(1024) char sm[];
    uint32_t sb = smem_u32(sm);
    int tid = threadIdx.x, wid = tid >> 5, lane = tid & 31;
    long aOff = blockIdx.y * 128;
    long bOff = blockIdx.x * 256;
    int warp_m = (wid & 1) * 64, warp_n = (wid >> 1) * 64;

    uint32_t hacc[4][8][2];
#pragma unroll
    for (int mt = 0; mt < 4; mt++)
#pragma unroll
        for (int nt = 0; nt < 8; nt++) { hacc[mt][nt][0] = 0u; hacc[mt][nt][1] = 0u; }

    int nkt = K >> 6;
    auto load_stage = [&](int s, int kt) {
        uint32_t base = sb + s * SSTF;
        long kb = (long)kt * 64;
#pragma unroll
        for (int it = 0; it < 4; it++) {
            int idx = tid + it * 256;
            int r = idx >> 3, c = idx & 7;
            uint32_t off = (uint32_t)(r * 128 + ((c ^ (r & 7)) << 4));
            CPA16(base + off, A + (aOff + r) * (long)K + kb + c * 8);
        }
#pragma unroll
        for (int it = 0; it < 8; it++) {
            int idx = tid + it * 256;
            int r = idx >> 3, c = idx & 7;
            uint32_t off = (uint32_t)(r * 128 + ((c ^ (r & 7)) << 4));
            CPA16(base + 16384 + off, B + (bOff + r) * (long)K + kb + c * 8);
        }
    };

    load_stage(0, 0);
    CP_COMMIT();

    for (int kt = 0; kt < nkt; kt++) {
        int s = kt & 1;
        if (kt + 1 < nkt) load_stage(s ^ 1, kt + 1);
        CP_COMMIT();
        CP_WAIT1();
        __syncthreads();

        uint32_t sA = sb + s * SSTF, sB = sA + 16384;
#pragma unroll
        for (int ks = 0; ks < 4; ks++) {
            uint32_t ah[4][4];
#pragma unroll
            for (int mt = 0; mt < 4; mt++) {
                int row = warp_m + mt * 16 + (lane & 15);
                int c16 = ks * 2 + (lane >> 4);
                uint32_t off = (uint32_t)(row * 128 + ((c16 ^ (row & 7)) << 4));
                LDSM4(ah[mt], sA + off);
            }
#pragma unroll
            for (int p = 0; p < 4; p++) {
                int row = warp_n + p * 16 + ((lane >> 4) << 3) + (lane & 7);
                int c16 = ks * 2 + ((lane >> 3) & 1);
                uint32_t off = (uint32_t)(row * 128 + ((c16 ^ (row & 7)) << 4));
                uint32_t bh[4];
                LDSM4(bh, sB + off);
#pragma unroll
                for (int mt = 0; mt < 4; mt++) {
                    mma16816h(hacc[mt][2*p],   ah[mt], bh[0], bh[1]);
                    mma16816h(hacc[mt][2*p+1], ah[mt], bh[2], bh[3]);
                }
            }
        }
        __syncthreads();
    }

    int rowBase = blockIdx.y*128 + warp_m + (lane >> 2);
    int colBase = blockIdx.x*256 + warp_n + (lane & 3) * 2;
#pragma unroll
    for (int mt = 0; mt < 4; mt++) {
#pragma unroll
        for (int nt = 0; nt < 8; nt++) {
#pragma unroll
            for (int hh = 0; hh < 2; hh++) {
                int row = rowBase + mt * 16 + hh * 8;
                int col = colBase + nt * 8;
                __half2 hv = *(__half2*)&hacc[mt][nt][hh];
                float x0 = __low2float(hv), x1 = __high2float(hv);
                if (bias) { x0 += bias[col]; x1 += bias[col + 1]; }
                if (act) { x0 = gelu_exact(x0); x1 = gelu_exact(x1); }
                long o = (long)row * ldc + col;
                if (C) *(float2*)(C + o) = make_float2(x0, x1);
                if (Ch) *(__half2*)(Ch + o) = __halves2half2(__float2half(x0), __float2half(x1));
            }
        }
    }
}

// ---------------- fp32 -> (hi,lo) fp16 --------------------------------------
__global__ void conv_hl(const float4* __restrict__ x, hf* __restrict__ h, hf* __restrict__ l) {
    long i = (long)blockIdx.x*256 + threadIdx.x;
    float4 v = x[i];
    hf h0,l0,h1,l1,h2,l2,h3,l3;
    split_hf(v.x,h0,l0); split_hf(v.y,h1,l1); split_hf(v.z,h2,l2); split_hf(v.w,h3,l3);
    __half2* hp = (__half2*)(h + 4*i);
    hp[0]=__halves2half2(h0,h1); hp[1]=__halves2half2(h2,h3);
    if (l) {
        __half2* lp = (__half2*)(l + 4*i);
        lp[0]=__halves2half2(l0,l1); lp[1]=__halves2half2(l2,l3);
    }
}

// ------------- transpose+split: in[z][R][Cc] -> out[z][Cc][R] (fp32 in) ------
__global__ void tconv(const float* __restrict__ in, hf* __restrict__ oh, hf* __restrict__ ol, int R, int Cc) {
    __shared__ float t[32][33];
    long base = (long)blockIdx.z * R * Cc;
    int c0 = blockIdx.x*32, r0 = blockIdx.y*32;
#pragma unroll
    for (int i = 0; i < 4; i++)
        t[threadIdx.y + i*8][threadIdx.x] = in[base + (long)(r0 + threadIdx.y + i*8)*Cc + c0 + threadIdx.x];
    __syncthreads();
#pragma unroll
    for (int i = 0; i < 4; i++) {
        int c = c0 + threadIdx.y + i*8, r = r0 + threadIdx.x;
        hf h, l; split_hf(t[threadIdx.x][threadIdx.y + i*8], h, l);
        long o = base + (long)c*R + r;
        oh[o] = h;
        if (ol) ol[o] = l;
    }
}

// ------------- transpose (fp16 in -> fp16 out): in[z][R][Cc] -> out[z][Cc][R]
__global__ void tconv_h(const hf* __restrict__ in, hf* __restrict__ oh, int R, int Cc) {
    __shared__ hf t[32][34];
    long base = (long)blockIdx.z * R * Cc;
    int c0 = blockIdx.x*32, r0 = blockIdx.y*32;
#pragma unroll
    for (int i = 0; i < 4; i++)
        t[threadIdx.y + i*8][threadIdx.x] = in[base + (long)(r0 + threadIdx.y + i*8)*Cc + c0 + threadIdx.x];
    __syncthreads();
#pragma unroll
    for (int i = 0; i < 4; i++) {
        int c = c0 + threadIdx.y + i*8, r = r0 + threadIdx.x;
        oh[base + (long)c*R + r] = t[threadIdx.x][threadIdx.y + i*8];
    }
}

// ------------------ causal softmax -> fp16 (hi only) -------------------------
__global__ void softmax_causal(const float* __restrict__ w, hf* __restrict__ aH) {
    long row = blockIdx.x;
    int t = (int)(row % Tq), tid = threadIdx.x;
    const float* p = w + row*(long)Tq;
    __shared__ float red[256];
    float vals[4], vmax = -1e30f;
#pragma unroll
    for (int i = 0; i < 4; i++) {
        int j = tid + i*256; float x = p[j]; vals[i] = x;
        if (j <= t && x > vmax) vmax = x;
    }
    red[tid] = vmax; __syncthreads();
    for (int s = 128; s > 0; s >>= 1) { if (tid < s) red[tid] = fmaxf(red[tid], red[tid+s]); __syncthreads(); }
    vmax = red[0]; __syncthreads();
    float sum = 0.f;
#pragma unroll
    for (int i = 0; i < 4; i++) {
        int j = tid + i*256;
        float e = (j <= t) ? expf(vals[i] - vmax) : 0.f;
        vals[i] = e; sum += e;
    }
    red[tid] = sum; __syncthreads();
    for (int s = 128; s > 0; s >>= 1) { if (tid < s) red[tid] += red[tid+s]; __syncthreads(); }
    float inv = 1.f / red[0];
#pragma unroll
    for (int i = 0; i < 4; i++)
        aH[row*(long)Tq + tid + i*256] = __float2half(vals[i]*inv);
}

// --------- beta[h][row] = dot(dbp[h,:], srcA[row,:])  (exact dbp handling) ---
__global__ void beta_k(const float* __restrict__ srcA, const float* __restrict__ dbp,
                       float* __restrict__ beta) {
    long row = blockIdx.x;
    int tid = threadIdx.x;
    const float* p = srcA + row*(long)Dq;
    __shared__ float red[256];
    float s[Hq] = {0.f, 0.f, 0.f, 0.f};
    for (int i = tid; i < Dq; i += 256) {
        float x = p[i];
        s[0] += x * dbp[i];
        s[1] += x * dbp[Dq + i];
        s[2] += x * dbp[2*Dq + i];
        s[3] += x * dbp[3*Dq + i];
    }
#pragma unroll
    for (int h = 0; h < Hq; h++) {
        red[tid] = s[h]; __syncthreads();
        for (int st = 128; st > 0; st >>= 1) { if (tid < st) red[tid] += red[tid+st]; __syncthreads(); }
        if (tid == 0) beta[(long)h*BT + row] = red[0];
        __syncthreads();
    }
}

// --- residual+LN: t = x(+y); out = ln_only ? ln(t) : t+ln(t); fp16 out opt ---
__global__ void resln(const float* __restrict__ x, const float* __restrict__ y,
                      const float* __restrict__ g, const float* __restrict__ b,
                      float* __restrict__ out, hf* __restrict__ oh, int ln_only) {
    long row = blockIdx.x;
    int tid = threadIdx.x;
    const float* px = x + row*(long)Dq;
    const float* py = y ? y + row*(long)Dq : nullptr;
    __shared__ float sh[Dq];
    __shared__ float red[256];
    float ls = 0.f;
    for (int i = tid; i < Dq; i += 256) { float t = px[i] + (py ? py[i] : 0.f); sh[i] = t; ls += t; }
    red[tid] = ls; __syncthreads();
    for (int s = 128; s > 0; s >>= 1) { if (tid < s) red[tid] += red[tid+s]; __syncthreads(); }
    float mean = red[0] * (1.0f/Dq); __syncthreads();
    float lv = 0.f;
    for (int i = tid; i < Dq; i += 256) { float d = sh[i]-mean; lv += d*d; }
    red[tid] = lv; __syncthreads();
    for (int s = 128; s > 0; s >>= 1) { if (tid < s) red[tid] += red[tid+s]; __syncthreads(); }
    float rstd = rsqrtf(red[0]*(1.0f/Dq) + 1e-5f);
    for (int i = tid; i < Dq; i += 256) {
        float t = sh[i];
        float l = (t - mean)*rstd*g[i] + b[i];
        float o = ln_only ? l : t + l;
        long oi = row*(long)Dq + i;
        if (out) out[oi] = o;
        if (oh) oh[oi] = __float2half(o);
    }
}

// --- fused double-LN: t = x+y; trgf = t+ln(t,g1,b1); ln2h = ln(trgf,g2,b2) ---
__global__ void resln2(const float* __restrict__ x, const float* __restrict__ y,
                       const float* __restrict__ g1, const float* __restrict__ b1,
                       const float* __restrict__ g2, const float* __restrict__ b2,
                       float* __restrict__ trgf, hf* __restrict__ ln2h) {
    long row = blockIdx.x;
    int tid = threadIdx.x;
    const float* px = x + row*(long)Dq;
    const float* py = y + row*(long)Dq;
    __shared__ float sh[Dq];
    __shared__ float red[256];
    float ls = 0.f;
    for (int i = tid; i < Dq; i += 256) { float t = px[i] + py[i]; sh[i] = t; ls += t; }
    red[tid] = ls; __syncthreads();
    for (int s = 128; s > 0; s >>= 1) { if (tid < s) red[tid] += red[tid+s]; __syncthreads(); }
    float mean = red[0] * (1.0f/Dq); __syncthreads();
    float lv = 0.f;
    for (int i = tid; i < Dq; i += 256) { float d = sh[i]-mean; lv += d*d; }
    red[tid] = lv; __syncthreads();
    for (int s = 128; s > 0; s >>= 1) { if (tid < s) red[tid] += red[tid+s]; __syncthreads(); }
    float rstd = rsqrtf(red[0]*(1.0f/Dq) + 1e-5f);
    __syncthreads();
    float ls2 = 0.f;
    for (int i = tid; i < Dq; i += 256) {
        float t = sh[i];
        float o = t + (t - mean)*rstd*g1[i] + b1[i];
        sh[i] = o; ls2 += o;
        trgf[row*(long)Dq + i] = o;
    }
    red[tid] = ls2; __syncthreads();
    for (int s = 128; s > 0; s >>= 1) { if (tid < s) red[tid] += red[tid+s]; __syncthreads(); }
    float mean2 = red[0] * (1.0f/Dq); __syncthreads();
    float lv2 = 0.f;
    for (int i = tid; i < Dq; i += 256) { float d = sh[i]-mean2; lv2 += d*d; }
    red[tid] = lv2; __syncthreads();
    for (int s = 128; s > 0; s >>= 1) { if (tid < s) red[tid] += red[tid+s]; __syncthreads(); }
    float rstd2 = rsqrtf(red[0]*(1.0f/Dq) + 1e-5f);
    for (int i = tid; i < Dq; i += 256)
        ln2h[row*(long)Dq + i] = __float2half((sh[i] - mean2)*rstd2*g2[i] + b2[i]);
}

// -----------------------------------------------------------------------------
extern "C" void kernel_launch(void* const* d_in, const int* in_sizes, int n_in,
                              void* d_out, int out_size)
{
    const float* src=(const float*)d_in[0]; const float* att=(const float*)d_in[1];
    const float* mWq=(const float*)d_in[2]; const float* mbq=(const float*)d_in[3];
    const float* mWk=(const float*)d_in[4]; const float* mbk=(const float*)d_in[5];
    const float* mWv=(const float*)d_in[6]; const float* dWp=(const float*)d_in[7];
    const float* dbp=(const float*)d_in[8]; const float* dWo=(const float*)d_in[9];
    const float* dbo=(const float*)d_in[10]; const float* fW1=(const float*)d_in[11];
    const float* fb1=(const float*)d_in[12]; const float* fW2=(const float*)d_in[13];
    const float* fb2=(const float*)d_in[14]; const float* g1=(const float*)d_in[15];
    const float* b1=(const float*)d_in[16]; const float* g2=(const float*)d_in[17];
    const float* b2=(const float*)d_in[18];
    float* out = (float*)d_out;

#define SYM(T,p,s) T p; cudaGetSymbolAddress((void**)&p, s)
    SYM(hf*,srcH,g_srcH); SYM(hf*,srcL,g_srcL); SYM(hf*,attH,g_attH);
    SYM(hf*,WqTH,g_WqTH); SYM(hf*,WqTL,g_WqTL); SYM(hf*,WkTH,g_WkTH); SYM(hf*,WkTL,g_WkTL);
    SYM(hf*,WvTH,g_WvTH);
    SYM(hf*,qH,g_qH); SYM(hf*,qL,g_qL); SYM(hf*,kH,g_kH); SYM(hf*,kL,g_kL);
    SYM(hf*,vH,g_vH); SYM(hf*,vTH,g_vTH);
    SYM(float*,w,g_w); SYM(hf*,aH,g_aH);
    SYM(float*,ocat,g_ocat); SYM(float*,srcA,g_srcA); SYM(hf*,srcAH,g_srcAH);
    SYM(hf*,dWpH,g_dWpH); SYM(hf*,M2T,g_M2T); SYM(float*,beta,g_beta);
    SYM(hf*,o2H,g_o2H); SYM(hf*,dWoTH,g_dWoTH);
    SYM(float*,o3,g_o3); SYM(float*,trgf,g_trgf); SYM(hf*,ln2H,g_ln2H);
    SYM(hf*,fW1TH,g_fW1TH); SYM(hf*,h1H,g_h1H);
    SYM(hf*,fW2TH,g_fW2TH); SYM(float*,ff,g_ff);

    // one-time creation of side stream + events (first call is NOT captured;
    // work per call is identical, so determinism holds)
    static cudaStream_t s2 = nullptr;
    static cudaEvent_t evFork, evSrc, evPrep, evV, evSrcA, evBeta;
    if (!s2) {
        cudaStreamCreateWithFlags(&s2, cudaStreamNonBlocking);
        cudaEventCreateWithFlags(&evFork, cudaEventDisableTiming);
        cudaEventCreateWithFlags(&evSrc,  cudaEventDisableTiming);
        cudaEventCreateWithFlags(&evPrep, cudaEventDisableTiming);
        cudaEventCreateWithFlags(&evV,    cudaEventDisableTiming);
        cudaEventCreateWithFlags(&evSrcA, cudaEventDisableTiming);
        cudaEventCreateWithFlags(&evBeta, cudaEventDisableTiming);
    }

    cudaFuncSetAttribute(gemm_tc<1>, cudaFuncAttributeMaxDynamicSharedMemorySize, 98304);
    cudaFuncSetAttribute(gemm_tc<3>, cudaFuncAttributeMaxDynamicSharedMemorySize, 196608);
    cudaFuncSetAttribute(gemm_ff,    cudaFuncAttributeMaxDynamicSharedMemorySize, SMEMF);
    dim3 tb(32, 8);
    const long TT=(long)Tq*Tq, TD=(long)Tq*Dq, BTD=(long)BT*Dq, BTHS=(long)BT*HSq, BTT=(long)Bq*Tq*Tq;

    // ---- fork side stream ----
    cudaEventRecord(evFork, 0);
    cudaStreamWaitEvent(s2, evFork, 0);

    // ---- main stream: critical path prep ----
    conv_hl<<<BTD/1024, 256>>>((const float4*)src, srcH, srcL);
    cudaEventRecord(evSrc, 0);
    tconv<<<dim3(HSq/32, Dq/32, Hq), tb>>>(mWq, WqTH, WqTL, Dq, HSq);
    tconv<<<dim3(HSq/32, Dq/32, Hq), tb>>>(mWk, WkTH, WkTL, Dq, HSq);

    // ---- side stream: independent prep + v chain ----
    conv_hl<<<BTHS/1024, 256, 0, s2>>>((const float4*)att, attH, nullptr);
    conv_hl<<<(Hq*HSq*Dq)/1024, 256, 0, s2>>>((const float4*)dWp, dWpH, nullptr);
    tconv<<<dim3(HSq/32, Dq/32, Hq), tb, 0, s2>>>(mWv, WvTH, nullptr, Dq, HSq);
    tconv<<<dim3(Dq/32, Dq/32, 1), tb, 0, s2>>>(dWo, dWoTH, nullptr, Dq, Dq);
    tconv<<<dim3(FFq/32, Dq/32, 1), tb, 0, s2>>>(fW1, fW1TH, nullptr, Dq, FFq);
    tconv<<<dim3(Dq/32, FFq/32, 1), tb, 0, s2>>>(fW2, fW2TH, nullptr, FFq, Dq);
    cudaEventRecord(evPrep, s2);
    cudaStreamWaitEvent(s2, evSrc, 0);
    gemm_tc<1><<<dim3(4,64,Hq), 256, 98304, s2>>>(srcH, nullptr, WvTH, nullptr, nullptr, nullptr, vH, nullptr,
        Dq, HSq, 1, 0,0, HSq,0, BTHS,0, 0,0, 1.0f, 0, 0);
    tconv_h<<<dim3(HSq/32, Tq/32, Hq*Bq), tb, 0, s2>>>(vH, vTH, Tq, HSq);
    cudaEventRecord(evV, s2);

    // ---- main: q, k, scores, softmax ----
    gemm_tc<3><<<dim3(4,64,Hq), 256, 196608>>>(srcH, srcL, WqTH, WqTL, mbq, nullptr, qH, qL,
        Dq, HSq, 1, 0,0, HSq,0, BTHS,0, HSq,0, 1.0f, 0, 0);
    gemm_tc<3><<<dim3(4,64,Hq), 256, 196608>>>(srcH, srcL, WkTH, WkTL, mbk, nullptr, kH, kL,
        Dq, HSq, 1, 0,0, HSq,0, BTHS,0, HSq,0, 1.0f, 0, 0);
    gemm_tc<3><<<dim3(4,8,Hq*Bq), 256, 196608>>>(qH, qL, kH, kL, nullptr, w, nullptr, nullptr,
        HSq, Tq, Bq, BT,Tq, BT,Tq, BTT,TT, 0,0, 32.0f, 0, 1);
    softmax_causal<<<Hq*Bq*Tq, 256>>>(w, aH);
    // AV needs vTH from s2
    cudaStreamWaitEvent(0, evV, 0);
    gemm_tc<1><<<dim3(4,8,Hq*Bq), 256, 98304>>>(aH, nullptr, vTH, nullptr, nullptr, ocat, nullptr, nullptr,
        Tq, Dq, Bq, Bq*Tq,Tq, Bq*HSq,HSq, (long)HSq,TD, 0,0, 1.0f, 0, 2);
    resln<<<BT, 256>>>(src, ocat, g1, b1, srcA, srcAH, 0);
    cudaEventRecord(evSrcA, 0);

    // side stream: beta (needs srcA)
    cudaStreamWaitEvent(s2, evSrcA, 0);
    beta_k<<<BT, 256, 0, s2>>>(srcA, dbp, beta);
    cudaEventRecord(evBeta, s2);

    // main: decoder chain (M2T needs dWpH from s2 prep)
    cudaStreamWaitEvent(0, evPrep, 0);
    gemm_tc<1><<<dim3(4,8,Hq*Bq), 256, 98304>>>(srcAH, nullptr, dWpH, nullptr, nullptr, nullptr, M2T, nullptr,
        Dq, Tq, Bq, 0,Tq, HSq,0, (long)Bq*TT,TT, 0,0, 1.0f, 0, 0);
    cudaStreamWaitEvent(0, evBeta, 0);
    gemm_tc<1><<<dim3(4,8,Hq*Bq), 256, 98304>>>(attH, nullptr, M2T, nullptr, beta, nullptr, o2H, nullptr,
        HSq, Dq, Bq, 0,Tq, Bq*Tq,Tq, (long)Tq,TD, (long)BT,(long)Tq, 1.0f, 0, 0);
    gemm_tc<1><<<dim3(16,64,1), 256, 98304>>>(o2H, nullptr, dWoTH, nullptr, dbo, o3, nullptr, nullptr,
        Dq, Dq, 1, 0,0, 0,0, 0,0, 0,0, 1.0f, 0, 0);
    resln2<<<BT, 256>>>(srcA, o3, g1, b1, g2, b2, trgf, ln2H);
    gemm_ff<<<dim3(80,64,1), 256, SMEMF>>>(ln2H, fW1TH, fb1, nullptr, h1H, Dq, FFq, 1);
    gemm_ff<<<dim3(16,64,1), 256, SMEMF>>>(h1H, fW2TH, fb2, ff, nullptr, FFq, Dq, 0);
    resln<<<BT, 256>>>(trgf, ff, g2, b2, out, nullptr, 1);
}